// round 12
// baseline (speedup 1.0000x reference)
#include <cuda_runtime.h>
#include <math.h>

#define BN   2
#define NPTS 8192
#define KNN  16
#define CIN  32
#define EIN  67      // 32 + 32 + 3
#define HID  128
#define COUT 64
#define TOT  (BN*NPTS)
#define FULLM 0xffffffffu
#define FMAX  3.402823466e38f

// (x,y)-cell sort for KNN
#define NBX   64
#define NBY   64
#define CELLS (NBX*NBY)          // 4096 per batch
#define XMIN  (-4.65f)
#define XSPAN 9.3f
#define BWX   (XSPAN/NBX)
#define INVBWX (NBX/XSPAN)
#define BWY   (XSPAN/NBY)
#define INVBWY (NBY/XSPAN)
#define WIN0  2                  // initial half-window in cells

// Scratch (no allocations allowed)
__device__ int    g_idx[TOT*KNN];
__device__ float  g_mid[TOT*COUT];
__device__ float4 g_vert4[TOT];
__device__ float  g_q[TOT*HID];
__device__ float  g_p[TOT*HID];
__device__ float4 g_stat[TOT];
__device__ int    g_ccnt[BN][CELLS];
__device__ int    g_cstart[BN][CELLS+1];   // CSR offsets (within batch)
__device__ int    g_ccur[BN][CELLS];
__device__ int    g_coltot[BN][NBX];
__device__ int    g_colbase[BN][NBX];
__device__ float4 g_sx4[TOT];              // cell-sorted points
__device__ int    g_ssid[TOT];             // sorted -> original GLOBAL index

// ---------------------------------------------------------------------------
__global__ void prep_kernel(const float* __restrict__ verts) {
    int i = blockIdx.x * blockDim.x + threadIdx.x;
    if (i < TOT) {
        float x = verts[i*3+0], y = verts[i*3+1], z = verts[i*3+2];
        g_vert4[i] = make_float4(x, y, z, x*x + y*y + z*z);
    }
    if (i < BN*CELLS) ((int*)g_ccnt)[i] = 0;
}

__device__ __forceinline__ int clampi(int v, int lo, int hi) {
    return v < lo ? lo : (v > hi ? hi : v);
}

__global__ void bin_kernel() {
    int i = blockIdx.x * blockDim.x + threadIdx.x;
    if (i >= TOT) return;
    float4 v = g_vert4[i];
    int bx = clampi((int)((v.x - XMIN) * INVBWX), 0, NBX-1);
    int by = clampi((int)((v.y - XMIN) * INVBWY), 0, NBY-1);
    atomicAdd(&g_ccnt[i >> 13][bx*NBY + by], 1);
}

// Per-column scan: block = (batch, x-column), 64 threads scan 64 y-cells.
__global__ void scanb_kernel() {
    __shared__ int s[NBY];
    int bb = blockIdx.x >> 6;       // /NBX
    int bx = blockIdx.x & (NBX-1);
    int t  = threadIdx.x;
    int v  = g_ccnt[bb][bx*NBY + t];
    s[t] = v;
    __syncthreads();
    for (int d = 1; d < NBY; d <<= 1) {
        int u = (t >= d) ? s[t - d] : 0;
        __syncthreads();
        s[t] += u;
        __syncthreads();
    }
    g_cstart[bb][bx*NBY + t] = s[t] - v;   // local (pre-colbase) exclusive
    if (t == NBY-1) g_coltot[bb][bx] = s[t];
}

// Scan the 64 column totals per batch (tiny).
__global__ void scanc_kernel() {
    __shared__ int s[NBX];
    int t = threadIdx.x;
    for (int bb = 0; bb < BN; bb++) {
        int v = g_coltot[bb][t];
        s[t] = v;
        __syncthreads();
        for (int d = 1; d < NBX; d <<= 1) {
            int u = (t >= d) ? s[t - d] : 0;
            __syncthreads();
            s[t] += u;
            __syncthreads();
        }
        g_colbase[bb][t] = s[t] - v;
        __syncthreads();
    }
}

// Add column bases -> global CSR offsets; init cursors; sentinel.
__global__ void fix_kernel() {
    int i = blockIdx.x * blockDim.x + threadIdx.x;
    if (i >= BN*CELLS) return;
    int bb = i / CELLS, c = i % CELLS;
    int st = g_cstart[bb][c] + g_colbase[bb][c / NBY];
    g_cstart[bb][c] = st;
    g_ccur[bb][c]   = st;
    if (c == 0) g_cstart[bb][CELLS] = NPTS;
}

__global__ void scatter_kernel() {
    int i = blockIdx.x * blockDim.x + threadIdx.x;
    if (i >= TOT) return;
    float4 v = g_vert4[i];
    int bb = i >> 13;
    int bx = clampi((int)((v.x - XMIN) * INVBWX), 0, NBX-1);
    int by = clampi((int)((v.y - XMIN) * INVBWY), 0, NBY-1);
    int slot = bb * NPTS + atomicAdd(&g_ccur[bb][bx*NBY + by], 1);
    g_sx4[slot]  = v;
    g_ssid[slot] = i;
}

// ---------------------------------------------------------------------------
// Scan sorted segment [a,b) through the warp's ascending lane-sorted best-32
// queue (batch-frozen threshold; identical distance formula as brute force).
// ---------------------------------------------------------------------------
__device__ __forceinline__ void scan_seg(int a, int b, int sbase, float4 qv,
                                         int lane, float& key, int& idx) {
    for (int i = a; i < b; i += 32) {
        int j = i + lane;
        float d = FMAX;
        if (j < b) {
            float4 c = __ldg(&g_sx4[sbase + j]);
            float dot = fmaf(qv.x, c.x, fmaf(qv.y, c.y, qv.z*c.z));
            d = fmaf(-2.0f, dot, qv.w + c.w);
        }
        float thb = __shfl_sync(FULLM, key, 15);
        unsigned mask = __ballot_sync(FULLM, d < thb);
        while (mask) {
            int src = __ffs(mask) - 1;
            mask &= mask - 1;
            float v  = __shfl_sync(FULLM, d, src);
            int   vi = i + src;
            float pk = __shfl_up_sync(FULLM, key, 1);
            int   pi = __shfl_up_sync(FULLM, idx, 1);
            if (v < key) {
                if (lane > 0 && v < pk) { key = pk; idx = pi; }
                else                    { key = v;  idx = vi; }
            }
        }
    }
}

// ---------------------------------------------------------------------------
// KNN: warp per query over (x,y)-sorted cells. Rectangular window; each
// x-column's y-range is ONE contiguous segment. Expand the side with the
// smallest boundary gap until d16 <= gap^2 (exact covering bound).
// ---------------------------------------------------------------------------
__global__ void __launch_bounds__(256) knn_kernel() {
    int tid  = threadIdx.x;
    int lane = tid & 31;
    int w    = tid >> 5;
    int gq   = blockIdx.x * 8 + w;
    int bb   = gq >> 13;
    int sbase = bb * NPTS;

    float4 qv = g_vert4[gq];
    int bx0 = clampi((int)((qv.x - XMIN) * INVBWX), 0, NBX-1);
    int by0 = clampi((int)((qv.y - XMIN) * INVBWY), 0, NBY-1);
    const int* cs = g_cstart[bb];

    int xlo = max(0, bx0 - WIN0), xhi = min(NBX-1, bx0 + WIN0);
    int ylo = max(0, by0 - WIN0), yhi = min(NBY-1, by0 + WIN0);

    float key = FMAX;
    int   idx = 0;

    for (int bx = xlo; bx <= xhi; bx++)
        scan_seg(cs[bx*NBY + ylo], cs[bx*NBY + yhi + 1], sbase, qv, lane, key, idx);

    for (;;) {
        float gxl = (xlo == 0)       ? FMAX : qv.x - (XMIN + xlo * BWX);
        float gxh = (xhi == NBX - 1) ? FMAX : (XMIN + (xhi + 1) * BWX) - qv.x;
        float gyl = (ylo == 0)       ? FMAX : qv.y - (XMIN + ylo * BWY);
        float gyh = (yhi == NBY - 1) ? FMAX : (XMIN + (yhi + 1) * BWY) - qv.y;
        float bnd = fminf(fminf(gxl, gxh), fminf(gyl, gyh));
        if (bnd > 1e37f) break;                       // everything scanned
        float th = __shfl_sync(FULLM, key, 15);
        if (th <= bnd * bnd) break;                   // exact stop bound
        if (gxl <= gxh && gxl <= gyl && gxl <= gyh) {
            xlo--;
            scan_seg(cs[xlo*NBY + ylo], cs[xlo*NBY + yhi + 1], sbase, qv, lane, key, idx);
        } else if (gxh <= gyl && gxh <= gyh) {
            xhi++;
            scan_seg(cs[xhi*NBY + ylo], cs[xhi*NBY + yhi + 1], sbase, qv, lane, key, idx);
        } else if (gyl <= gyh) {
            ylo--;
            for (int bx = xlo; bx <= xhi; bx++)
                scan_seg(cs[bx*NBY + ylo], cs[bx*NBY + ylo + 1], sbase, qv, lane, key, idx);
        } else {
            yhi++;
            for (int bx = xlo; bx <= xhi; bx++)
                scan_seg(cs[bx*NBY + yhi], cs[bx*NBY + yhi + 1], sbase, qv, lane, key, idx);
        }
    }

    if (lane < KNN) g_idx[gq*KNN + lane] = g_ssid[sbase + idx];
}

// ---------------------------------------------------------------------------
// Precompute Q[n], P[n] and their channel sums / sum-of-squares.
// ---------------------------------------------------------------------------
__global__ void __launch_bounds__(256) precomp_kernel(
    const float* __restrict__ verts, const float* __restrict__ feat,
    const float* __restrict__ W1, const float* __restrict__ b1)
{
    __shared__ float sW1[EIN*HID];   // 34.3KB
    int tid = threadIdx.x, lane = tid & 31, w = tid >> 5;
    for (int e = tid; e < EIN*HID; e += 256) sW1[e] = W1[e];
    __syncthreads();

    int p = blockIdx.x * 8 + w;
    float4 f4 = make_float4(0.f,0.f,0.f,0.f);
    if (lane < 8) f4 = *(const float4*)&feat[p*CIN + lane*4];
    float vx = verts[p*3+0], vy = verts[p*3+1], vz = verts[p*3+2];

    int c = lane*4;
    float4 q  = make_float4(0.f,0.f,0.f,0.f);
    float4 pp = *(const float4*)&b1[c];

#pragma unroll
    for (int src = 0; src < 8; src++) {
        float fx = __shfl_sync(FULLM, f4.x, src);
        float fy = __shfl_sync(FULLM, f4.y, src);
        float fz = __shfl_sync(FULLM, f4.z, src);
        float fw = __shfl_sync(FULLM, f4.w, src);
        float fv[4] = {fx, fy, fz, fw};
        int k0 = src*4;
#pragma unroll
        for (int kk = 0; kk < 4; kk++) {
            int k = k0 + kk;
            float4 wa = *(const float4*)&sW1[k*HID + c];
            float4 wb = *(const float4*)&sW1[(CIN + k)*HID + c];
            q.x  = fmaf(fv[kk], wa.x, q.x);  q.y  = fmaf(fv[kk], wa.y, q.y);
            q.z  = fmaf(fv[kk], wa.z, q.z);  q.w  = fmaf(fv[kk], wa.w, q.w);
            pp.x = fmaf(fv[kk], wb.x, pp.x); pp.y = fmaf(fv[kk], wb.y, pp.y);
            pp.z = fmaf(fv[kk], wb.z, pp.z); pp.w = fmaf(fv[kk], wb.w, pp.w);
        }
    }
    float vv[3] = {vx, vy, vz};
#pragma unroll
    for (int k = 0; k < 3; k++) {
        float4 wc = *(const float4*)&sW1[(2*CIN + k)*HID + c];
        q.x  = fmaf(vv[k],  wc.x, q.x);  q.y  = fmaf(vv[k],  wc.y, q.y);
        q.z  = fmaf(vv[k],  wc.z, q.z);  q.w  = fmaf(vv[k],  wc.w, q.w);
        pp.x = fmaf(-vv[k], wc.x, pp.x); pp.y = fmaf(-vv[k], wc.y, pp.y);
        pp.z = fmaf(-vv[k], wc.z, pp.z); pp.w = fmaf(-vv[k], wc.w, pp.w);
    }
    *(float4*)&g_q[p*HID + c] = q;
    *(float4*)&g_p[p*HID + c] = pp;

    float sq  = (q.x + q.y) + (q.z + q.w);
    float sq2 = fmaf(q.x,q.x, fmaf(q.y,q.y, fmaf(q.z,q.z, q.w*q.w)));
    float sp  = (pp.x + pp.y) + (pp.z + pp.w);
    float sp2 = fmaf(pp.x,pp.x, fmaf(pp.y,pp.y, fmaf(pp.z,pp.z, pp.w*pp.w)));
#pragma unroll
    for (int off = 16; off; off >>= 1) {
        sq  += __shfl_xor_sync(FULLM, sq,  off);
        sq2 += __shfl_xor_sync(FULLM, sq2, off);
        sp  += __shfl_xor_sync(FULLM, sp,  off);
        sp2 += __shfl_xor_sync(FULLM, sp2, off);
    }
    if (lane == 0) g_stat[p] = make_float4(sq, sq2, sp, sp2);
}

// ---------------------------------------------------------------------------
__device__ __forceinline__ float gelu_fast(float x) {
    float z2 = 1.5957691216057308f * fmaf(0.044715f * x * x, x, x);
    float e  = __expf(z2);
    float r  = __fdividef(1.0f, e + 1.0f);
    return x - x * r;
}

// ---------------------------------------------------------------------------
// Edge kernel: warp per point. LN stats via precomputed sums; one
// dot-reduction per edge.
// ---------------------------------------------------------------------------
__global__ void __launch_bounds__(256) edge_kernel(
    const float* __restrict__ g1, const float* __restrict__ be1,
    const float* __restrict__ W2, const float* __restrict__ b2)
{
    __shared__ float sW2[HID*COUT];   // 32KB
    int tid = threadIdx.x, lane = tid & 31, w = tid >> 5;
    for (int e = tid; e < HID*COUT; e += 256) sW2[e] = W2[e];
    __syncthreads();

    int p = blockIdx.x * 8 + w;
    int myidx = (lane < KNN) ? g_idx[p*KNN + lane] : 0;
    int c = lane * 4;

    float4 P4  = *(const float4*)&g_p[p*HID + c];
    float4 g1v = *(const float4*)&g1[c];
    float4 bev = *(const float4*)&be1[c];
    float4 stP = g_stat[p];
    float4 stN = __ldg(&g_stat[myidx]);
    float sumn = stN.x + stP.z;
    float bsqn = stN.y + stP.w;

    float4 accG = make_float4(0.f,0.f,0.f,0.f);

    int nb0 = __shfl_sync(FULLM, myidx, 0);
    int nb1 = __shfl_sync(FULLM, myidx, 1);
    float4 qa = __ldg((const float4*)&g_q[nb0*HID + c]);
    float4 qb = __ldg((const float4*)&g_q[nb1*HID + c]);

#pragma unroll
    for (int n = 0; n < KNN; n += 2) {
        float4 h0, h1;
        h0.x = qa.x + P4.x; h0.y = qa.y + P4.y; h0.z = qa.z + P4.z; h0.w = qa.w + P4.w;
        h1.x = qb.x + P4.x; h1.y = qb.y + P4.y; h1.z = qb.z + P4.z; h1.w = qb.w + P4.w;
        float dp0 = fmaf(qa.x,P4.x, fmaf(qa.y,P4.y, fmaf(qa.z,P4.z, qa.w*P4.w)));
        float dp1 = fmaf(qb.x,P4.x, fmaf(qb.y,P4.y, fmaf(qb.z,P4.z, qb.w*P4.w)));
        if (n + 2 < KNN) {
            int na  = __shfl_sync(FULLM, myidx, n+2);
            int nbx = __shfl_sync(FULLM, myidx, n+3);
            qa = __ldg((const float4*)&g_q[na*HID + c]);
            qb = __ldg((const float4*)&g_q[nbx*HID + c]);
        }
#pragma unroll
        for (int off = 16; off; off >>= 1) {
            dp0 += __shfl_xor_sync(FULLM, dp0, off);
            dp1 += __shfl_xor_sync(FULLM, dp1, off);
        }
        float sum0 = __shfl_sync(FULLM, sumn, n);
        float sum1 = __shfl_sync(FULLM, sumn, n+1);
        float bb0  = __shfl_sync(FULLM, bsqn, n);
        float bb1  = __shfl_sync(FULLM, bsqn, n+1);

        float mu0 = sum0 * (1.f/HID);
        float e20 = fmaf(2.0f, dp0, bb0) * (1.f/HID);
        float rs0 = rsqrtf(e20 - mu0*mu0 + 1e-5f);
        float mu1 = sum1 * (1.f/HID);
        float e21 = fmaf(2.0f, dp1, bb1) * (1.f/HID);
        float rs1 = rsqrtf(e21 - mu1*mu1 + 1e-5f);

        accG.x += gelu_fast(fmaf((h0.x - mu0)*rs0, g1v.x, bev.x));
        accG.y += gelu_fast(fmaf((h0.y - mu0)*rs0, g1v.y, bev.y));
        accG.z += gelu_fast(fmaf((h0.z - mu0)*rs0, g1v.z, bev.z));
        accG.w += gelu_fast(fmaf((h0.w - mu0)*rs0, g1v.w, bev.w));
        accG.x += gelu_fast(fmaf((h1.x - mu1)*rs1, g1v.x, bev.x));
        accG.y += gelu_fast(fmaf((h1.y - mu1)*rs1, g1v.y, bev.y));
        accG.z += gelu_fast(fmaf((h1.z - mu1)*rs1, g1v.z, bev.z));
        accG.w += gelu_fast(fmaf((h1.w - mu1)*rs1, g1v.w, bev.w));
    }
    accG.x *= (1.f/KNN); accG.y *= (1.f/KNN);
    accG.z *= (1.f/KNN); accG.w *= (1.f/KNN);

    float m0 = __ldg(&b2[lane]);
    float m1 = __ldg(&b2[lane + 32]);
#pragma unroll
    for (int src = 0; src < 32; src++) {
        float gx = __shfl_sync(FULLM, accG.x, src);
        float gy = __shfl_sync(FULLM, accG.y, src);
        float gz = __shfl_sync(FULLM, accG.z, src);
        float gw = __shfl_sync(FULLM, accG.w, src);
        int k0 = src * 4;
        m0 = fmaf(gx, sW2[(k0+0)*COUT + lane], m0);
        m0 = fmaf(gy, sW2[(k0+1)*COUT + lane], m0);
        m0 = fmaf(gz, sW2[(k0+2)*COUT + lane], m0);
        m0 = fmaf(gw, sW2[(k0+3)*COUT + lane], m0);
        m1 = fmaf(gx, sW2[(k0+0)*COUT + lane + 32], m1);
        m1 = fmaf(gy, sW2[(k0+1)*COUT + lane + 32], m1);
        m1 = fmaf(gz, sW2[(k0+2)*COUT + lane + 32], m1);
        m1 = fmaf(gw, sW2[(k0+3)*COUT + lane + 32], m1);
    }
    g_mid[p*COUT + lane]      = m0;
    g_mid[p*COUT + lane + 32] = m1;
}

// ---------------------------------------------------------------------------
// MLP2 fused: 64 points per block, grid 256.
// ---------------------------------------------------------------------------
#define M2PTS 64
#define SMEM2_FLOATS (COUT*M2PTS + COUT*HID + HID*COUT)  // 20480

__global__ void __launch_bounds__(256, 2) mlp2_kernel(
    const float* __restrict__ Wo1, const float* __restrict__ bo1,
    const float* __restrict__ go,  const float* __restrict__ beo,
    const float* __restrict__ Wo2, const float* __restrict__ bo2,
    float* __restrict__ out)
{
    extern __shared__ float sm[];
    float* sAt  = sm;
    float* sWo1 = sm + COUT*M2PTS;
    float* sH   = sm;                          // aliases sAt+sWo1
    float* sWo2 = sm + COUT*M2PTS + COUT*HID;

    int tid = threadIdx.x;
    int r0  = blockIdx.x * M2PTS;

    for (int e = tid; e < COUT*HID; e += 256) sWo1[e] = Wo1[e];
    for (int e = tid; e < HID*COUT; e += 256) sWo2[e] = Wo2[e];
    for (int e = tid; e < COUT*M2PTS; e += 256) {
        int r = e & (M2PTS-1), k = e >> 6;
        sAt[k*M2PTS + r] = g_mid[(r0 + r)*COUT + k];
    }
    __syncthreads();

    int tx = tid & 15, ty = tid >> 4;

    float acc[4][8];
#pragma unroll
    for (int i = 0; i < 4; i++)
#pragma unroll
        for (int j = 0; j < 8; j++) acc[i][j] = 0.f;

    for (int k = 0; k < COUT; k++) {
        float4 a4 = *(const float4*)&sAt[k*M2PTS + ty*4];
        float4 c0 = *(const float4*)&sWo1[k*HID + tx*8];
        float4 c1 = *(const float4*)&sWo1[k*HID + tx*8 + 4];
        float a[4] = {a4.x,a4.y,a4.z,a4.w};
        float wv[8] = {c0.x,c0.y,c0.z,c0.w,c1.x,c1.y,c1.z,c1.w};
#pragma unroll
        for (int i = 0; i < 4; i++)
#pragma unroll
            for (int j = 0; j < 8; j++)
                acc[i][j] = fmaf(a[i], wv[j], acc[i][j]);
    }

    __syncthreads();

    float b1j[8], gj[8], bej[8];
#pragma unroll
    for (int j = 0; j < 8; j++) {
        int col = tx*8 + j;
        b1j[j] = bo1[col]; gj[j] = go[col]; bej[j] = beo[col];
    }
#pragma unroll
    for (int i = 0; i < 4; i++) {
        float ps = 0.f, ps2 = 0.f;
#pragma unroll
        for (int j = 0; j < 8; j++) {
            float h = acc[i][j] + b1j[j];
            acc[i][j] = h;
            ps += h; ps2 = fmaf(h, h, ps2);
        }
#pragma unroll
        for (int off = 8; off; off >>= 1) {
            ps  += __shfl_xor_sync(FULLM, ps,  off);
            ps2 += __shfl_xor_sync(FULLM, ps2, off);
        }
        float mu  = ps  * (1.f/HID);
        float var = ps2 * (1.f/HID) - mu*mu;
        float rs  = rsqrtf(var + 1e-5f);
        float o[8];
#pragma unroll
        for (int j = 0; j < 8; j++)
            o[j] = gelu_fast(fmaf((acc[i][j] - mu)*rs, gj[j], bej[j]));
        int row = ty*4 + i;
        *(float4*)&sH[row*132 + tx*8]     = make_float4(o[0],o[1],o[2],o[3]);
        *(float4*)&sH[row*132 + tx*8 + 4] = make_float4(o[4],o[5],o[6],o[7]);
    }
    __syncthreads();

    float acc2[4][4];
#pragma unroll
    for (int i = 0; i < 4; i++)
#pragma unroll
        for (int j = 0; j < 4; j++) acc2[i][j] = 0.f;

    for (int k = 0; k < HID; k += 4) {
        float4 w0 = *(const float4*)&sWo2[(k+0)*COUT + tx*4];
        float4 w1 = *(const float4*)&sWo2[(k+1)*COUT + tx*4];
        float4 w2 = *(const float4*)&sWo2[(k+2)*COUT + tx*4];
        float4 w3 = *(const float4*)&sWo2[(k+3)*COUT + tx*4];
#pragma unroll
        for (int i = 0; i < 4; i++) {
            float4 av = *(const float4*)&sH[(ty*4+i)*132 + k];
            acc2[i][0] = fmaf(av.x, w0.x, fmaf(av.y, w1.x, fmaf(av.z, w2.x, fmaf(av.w, w3.x, acc2[i][0]))));
            acc2[i][1] = fmaf(av.x, w0.y, fmaf(av.y, w1.y, fmaf(av.z, w2.y, fmaf(av.w, w3.y, acc2[i][1]))));
            acc2[i][2] = fmaf(av.x, w0.z, fmaf(av.y, w1.z, fmaf(av.z, w2.z, fmaf(av.w, w3.z, acc2[i][2]))));
            acc2[i][3] = fmaf(av.x, w0.w, fmaf(av.y, w1.w, fmaf(av.z, w2.w, fmaf(av.w, w3.w, acc2[i][3]))));
        }
    }

    float b2j[4];
#pragma unroll
    for (int j = 0; j < 4; j++) b2j[j] = bo2[tx*4 + j];
#pragma unroll
    for (int i = 0; i < 4; i++) {
        int row = r0 + ty*4 + i;
#pragma unroll
        for (int j = 0; j < 4; j++)
            out[row*COUT + tx*4 + j] = acc2[i][j] + b2j[j];
    }
}

// ---------------------------------------------------------------------------
extern "C" void kernel_launch(void* const* d_in, const int* in_sizes, int n_in,
                              void* d_out, int out_size) {
    const float* verts = (const float*)d_in[0];
    const float* feat  = (const float*)d_in[1];
    const float* W1    = (const float*)d_in[2];
    const float* b1    = (const float*)d_in[3];
    const float* g1    = (const float*)d_in[4];
    const float* be1   = (const float*)d_in[5];
    const float* W2    = (const float*)d_in[6];
    const float* b2    = (const float*)d_in[7];
    const float* Wo1   = (const float*)d_in[8];
    const float* bo1   = (const float*)d_in[9];
    const float* go    = (const float*)d_in[10];
    const float* beo   = (const float*)d_in[11];
    const float* Wo2   = (const float*)d_in[12];
    const float* bo2   = (const float*)d_in[13];
    float* out = (float*)d_out;

    const int smem2 = SMEM2_FLOATS * 4;   // 81920
    cudaFuncSetAttribute(mlp2_kernel, cudaFuncAttributeMaxDynamicSharedMemorySize, smem2);

    prep_kernel<<<(TOT + 255)/256, 256>>>(verts);
    bin_kernel<<<(TOT + 255)/256, 256>>>();
    scanb_kernel<<<BN*NBX, NBY>>>();
    scanc_kernel<<<1, NBX>>>();
    fix_kernel<<<(BN*CELLS + 255)/256, 256>>>();
    scatter_kernel<<<(TOT + 255)/256, 256>>>();
    knn_kernel<<<TOT/8, 256>>>();
    precomp_kernel<<<TOT/8, 256>>>(verts, feat, W1, b1);
    edge_kernel<<<TOT/8, 256>>>(g1, be1, W2, b2);
    mlp2_kernel<<<TOT/M2PTS, 256, smem2>>>(Wo1, bo1, go, beo, Wo2, bo2, out);
}

// round 13
// speedup vs baseline: 1.1244x; 1.1244x over previous
#include <cuda_runtime.h>
#include <math.h>

#define BN   2
#define NPTS 8192
#define KNN  16
#define CIN  32
#define EIN  67      // 32 + 32 + 3
#define HID  128
#define COUT 64
#define TOT  (BN*NPTS)
#define FULLM 0xffffffffu
#define FMAX  3.402823466e38f

// (x,y)-cell sort for KNN
#define NBX   48
#define NBY   48
#define CELLS (NBX*NBY)          // 2304 per batch
#define XMIN  (-4.65f)
#define XSPAN 9.3f
#define BWX   (XSPAN/NBX)
#define INVBWX (NBX/XSPAN)
#define BWY   (XSPAN/NBY)
#define INVBWY (NBY/XSPAN)
#define WIN0  1                  // initial half-window in cells (3x3)

// Scratch (no allocations allowed)
__device__ int    g_idx[TOT*KNN];
__device__ float  g_mid[TOT*COUT];
__device__ float4 g_vert4[TOT];
__device__ float  g_q[TOT*HID];
__device__ float  g_p[TOT*HID];
__device__ float4 g_stat[TOT];
__device__ int    g_ccnt[BN][CELLS];
__device__ int    g_cstart[BN][CELLS+1];
__device__ int    g_ccur[BN][CELLS];
__device__ float4 g_sx4[TOT];              // cell-sorted points
__device__ int    g_ssid[TOT];             // sorted -> original GLOBAL index

// ---------------------------------------------------------------------------
__global__ void prep_kernel(const float* __restrict__ verts) {
    int i = blockIdx.x * blockDim.x + threadIdx.x;
    if (i < TOT) {
        float x = verts[i*3+0], y = verts[i*3+1], z = verts[i*3+2];
        g_vert4[i] = make_float4(x, y, z, x*x + y*y + z*z);
    }
    if (i < BN*CELLS) ((int*)g_ccnt)[i] = 0;
}

__device__ __forceinline__ int clampi(int v, int lo, int hi) {
    return v < lo ? lo : (v > hi ? hi : v);
}

__global__ void bin_kernel() {
    int i = blockIdx.x * blockDim.x + threadIdx.x;
    if (i >= TOT) return;
    float4 v = g_vert4[i];
    int bx = clampi((int)((v.x - XMIN) * INVBWX), 0, NBX-1);
    int by = clampi((int)((v.y - XMIN) * INVBWY), 0, NBY-1);
    atomicAdd(&g_ccnt[i >> 13][bx*NBY + by], 1);
}

// One block per batch, 1024 threads, 3 cells/thread + block-wide scan.
__global__ void scan_kernel() {
    __shared__ int s[1024];
    int bb = blockIdx.x, t = threadIdx.x;
    int lo = t*3, hi = min(lo+3, CELLS);
    int loc[3]; int sum = 0;
    for (int i = lo; i < hi; i++) { loc[i-lo] = g_ccnt[bb][i]; sum += loc[i-lo]; }
    s[t] = sum;
    __syncthreads();
    for (int d = 1; d < 1024; d <<= 1) {
        int u = (t >= d) ? s[t-d] : 0;
        __syncthreads();
        s[t] += u;
        __syncthreads();
    }
    int run = s[t] - sum;
    for (int i = lo; i < hi; i++) {
        g_cstart[bb][i] = run;
        g_ccur[bb][i]   = run;
        run += loc[i-lo];
    }
    if (t == 1023) g_cstart[bb][CELLS] = NPTS;
}

__global__ void scatter_kernel() {
    int i = blockIdx.x * blockDim.x + threadIdx.x;
    if (i >= TOT) return;
    float4 v = g_vert4[i];
    int bb = i >> 13;
    int bx = clampi((int)((v.x - XMIN) * INVBWX), 0, NBX-1);
    int by = clampi((int)((v.y - XMIN) * INVBWY), 0, NBY-1);
    int slot = bb * NPTS + atomicAdd(&g_ccur[bb][bx*NBY + by], 1);
    g_sx4[slot]  = v;
    g_ssid[slot] = i;
}

// ---------------------------------------------------------------------------
// Scan sorted segment [a,b) through the warp's ascending lane-sorted best-32
// queue (batch-frozen threshold; identical distance formula as brute force).
// ---------------------------------------------------------------------------
__device__ __forceinline__ void scan_seg(int a, int b, int sbase, float4 qv,
                                         int lane, float& key, int& idx) {
    for (int i = a; i < b; i += 32) {
        int j = i + lane;
        float d = FMAX;
        if (j < b) {
            float4 c = __ldg(&g_sx4[sbase + j]);
            float dot = fmaf(qv.x, c.x, fmaf(qv.y, c.y, qv.z*c.z));
            d = fmaf(-2.0f, dot, qv.w + c.w);
        }
        float thb = __shfl_sync(FULLM, key, 15);
        unsigned mask = __ballot_sync(FULLM, d < thb);
        while (mask) {
            int src = __ffs(mask) - 1;
            mask &= mask - 1;
            float v  = __shfl_sync(FULLM, d, src);
            int   vi = i + src;
            float pk = __shfl_up_sync(FULLM, key, 1);
            int   pi = __shfl_up_sync(FULLM, idx, 1);
            if (v < key) {
                if (lane > 0 && v < pk) { key = pk; idx = pi; }
                else                    { key = v;  idx = vi; }
            }
        }
    }
}

// ---------------------------------------------------------------------------
// KNN: warp per query over (x,y)-sorted cells, CSR staged in SMEM (all warps
// of a block share one batch). Rectangular window expansion with exact
// covering stop bound.
// ---------------------------------------------------------------------------
__global__ void __launch_bounds__(256) knn_kernel() {
    __shared__ int scs[CELLS+1];     // 9.2KB
    int tid  = threadIdx.x;
    int lane = tid & 31;
    int w    = tid >> 5;
    int gq   = blockIdx.x * 8 + w;
    int bb   = gq >> 13;
    int sbase = bb * NPTS;

    for (int i = tid; i <= CELLS; i += 256) scs[i] = g_cstart[bb][i];
    __syncthreads();

    float4 qv = g_vert4[gq];
    int bx0 = clampi((int)((qv.x - XMIN) * INVBWX), 0, NBX-1);
    int by0 = clampi((int)((qv.y - XMIN) * INVBWY), 0, NBY-1);

    int xlo = max(0, bx0 - WIN0), xhi = min(NBX-1, bx0 + WIN0);
    int ylo = max(0, by0 - WIN0), yhi = min(NBY-1, by0 + WIN0);

    float key = FMAX;
    int   idx = 0;

    for (int bx = xlo; bx <= xhi; bx++)
        scan_seg(scs[bx*NBY + ylo], scs[bx*NBY + yhi + 1], sbase, qv, lane, key, idx);

    for (;;) {
        float gxl = (xlo == 0)       ? FMAX : qv.x - (XMIN + xlo * BWX);
        float gxh = (xhi == NBX - 1) ? FMAX : (XMIN + (xhi + 1) * BWX) - qv.x;
        float gyl = (ylo == 0)       ? FMAX : qv.y - (XMIN + ylo * BWY);
        float gyh = (yhi == NBY - 1) ? FMAX : (XMIN + (yhi + 1) * BWY) - qv.y;
        float bnd = fminf(fminf(gxl, gxh), fminf(gyl, gyh));
        if (bnd > 1e37f) break;                       // everything scanned
        float th = __shfl_sync(FULLM, key, 15);
        if (th <= bnd * bnd) break;                   // exact stop bound
        if (gxl <= gxh && gxl <= gyl && gxl <= gyh) {
            xlo--;
            scan_seg(scs[xlo*NBY + ylo], scs[xlo*NBY + yhi + 1], sbase, qv, lane, key, idx);
        } else if (gxh <= gyl && gxh <= gyh) {
            xhi++;
            scan_seg(scs[xhi*NBY + ylo], scs[xhi*NBY + yhi + 1], sbase, qv, lane, key, idx);
        } else if (gyl <= gyh) {
            ylo--;
            for (int bx = xlo; bx <= xhi; bx++)
                scan_seg(scs[bx*NBY + ylo], scs[bx*NBY + ylo + 1], sbase, qv, lane, key, idx);
        } else {
            yhi++;
            for (int bx = xlo; bx <= xhi; bx++)
                scan_seg(scs[bx*NBY + yhi], scs[bx*NBY + yhi + 1], sbase, qv, lane, key, idx);
        }
    }

    if (lane < KNN) g_idx[gq*KNN + lane] = g_ssid[sbase + idx];
}

// ---------------------------------------------------------------------------
// Precompute Q[n], P[n] and their channel sums / sum-of-squares.
// ---------------------------------------------------------------------------
__global__ void __launch_bounds__(256) precomp_kernel(
    const float* __restrict__ verts, const float* __restrict__ feat,
    const float* __restrict__ W1, const float* __restrict__ b1)
{
    __shared__ float sW1[EIN*HID];   // 34.3KB
    int tid = threadIdx.x, lane = tid & 31, w = tid >> 5;
    for (int e = tid; e < EIN*HID; e += 256) sW1[e] = W1[e];
    __syncthreads();

    int p = blockIdx.x * 8 + w;
    float4 f4 = make_float4(0.f,0.f,0.f,0.f);
    if (lane < 8) f4 = *(const float4*)&feat[p*CIN + lane*4];
    float vx = verts[p*3+0], vy = verts[p*3+1], vz = verts[p*3+2];

    int c = lane*4;
    float4 q  = make_float4(0.f,0.f,0.f,0.f);
    float4 pp = *(const float4*)&b1[c];

#pragma unroll
    for (int src = 0; src < 8; src++) {
        float fx = __shfl_sync(FULLM, f4.x, src);
        float fy = __shfl_sync(FULLM, f4.y, src);
        float fz = __shfl_sync(FULLM, f4.z, src);
        float fw = __shfl_sync(FULLM, f4.w, src);
        float fv[4] = {fx, fy, fz, fw};
        int k0 = src*4;
#pragma unroll
        for (int kk = 0; kk < 4; kk++) {
            int k = k0 + kk;
            float4 wa = *(const float4*)&sW1[k*HID + c];
            float4 wb = *(const float4*)&sW1[(CIN + k)*HID + c];
            q.x  = fmaf(fv[kk], wa.x, q.x);  q.y  = fmaf(fv[kk], wa.y, q.y);
            q.z  = fmaf(fv[kk], wa.z, q.z);  q.w  = fmaf(fv[kk], wa.w, q.w);
            pp.x = fmaf(fv[kk], wb.x, pp.x); pp.y = fmaf(fv[kk], wb.y, pp.y);
            pp.z = fmaf(fv[kk], wb.z, pp.z); pp.w = fmaf(fv[kk], wb.w, pp.w);
        }
    }
    float vv[3] = {vx, vy, vz};
#pragma unroll
    for (int k = 0; k < 3; k++) {
        float4 wc = *(const float4*)&sW1[(2*CIN + k)*HID + c];
        q.x  = fmaf(vv[k],  wc.x, q.x);  q.y  = fmaf(vv[k],  wc.y, q.y);
        q.z  = fmaf(vv[k],  wc.z, q.z);  q.w  = fmaf(vv[k],  wc.w, q.w);
        pp.x = fmaf(-vv[k], wc.x, pp.x); pp.y = fmaf(-vv[k], wc.y, pp.y);
        pp.z = fmaf(-vv[k], wc.z, pp.z); pp.w = fmaf(-vv[k], wc.w, pp.w);
    }
    *(float4*)&g_q[p*HID + c] = q;
    *(float4*)&g_p[p*HID + c] = pp;

    float sq  = (q.x + q.y) + (q.z + q.w);
    float sq2 = fmaf(q.x,q.x, fmaf(q.y,q.y, fmaf(q.z,q.z, q.w*q.w)));
    float sp  = (pp.x + pp.y) + (pp.z + pp.w);
    float sp2 = fmaf(pp.x,pp.x, fmaf(pp.y,pp.y, fmaf(pp.z,pp.z, pp.w*pp.w)));
#pragma unroll
    for (int off = 16; off; off >>= 1) {
        sq  += __shfl_xor_sync(FULLM, sq,  off);
        sq2 += __shfl_xor_sync(FULLM, sq2, off);
        sp  += __shfl_xor_sync(FULLM, sp,  off);
        sp2 += __shfl_xor_sync(FULLM, sp2, off);
    }
    if (lane == 0) g_stat[p] = make_float4(sq, sq2, sp, sp2);
}

// ---------------------------------------------------------------------------
__device__ __forceinline__ float gelu_fast(float x) {
    float z2 = 1.5957691216057308f * fmaf(0.044715f * x * x, x, x);
    float e  = __expf(z2);
    float r  = __fdividef(1.0f, e + 1.0f);
    return x - x * r;
}

// ---------------------------------------------------------------------------
// Edge kernel: warp per point. LN stats via precomputed sums; one
// dot-reduction per edge.
// ---------------------------------------------------------------------------
__global__ void __launch_bounds__(256) edge_kernel(
    const float* __restrict__ g1, const float* __restrict__ be1,
    const float* __restrict__ W2, const float* __restrict__ b2)
{
    __shared__ float sW2[HID*COUT];   // 32KB
    int tid = threadIdx.x, lane = tid & 31, w = tid >> 5;
    for (int e = tid; e < HID*COUT; e += 256) sW2[e] = W2[e];
    __syncthreads();

    int p = blockIdx.x * 8 + w;
    int myidx = (lane < KNN) ? g_idx[p*KNN + lane] : 0;
    int c = lane * 4;

    float4 P4  = *(const float4*)&g_p[p*HID + c];
    float4 g1v = *(const float4*)&g1[c];
    float4 bev = *(const float4*)&be1[c];
    float4 stP = g_stat[p];
    float4 stN = __ldg(&g_stat[myidx]);
    float sumn = stN.x + stP.z;
    float bsqn = stN.y + stP.w;

    float4 accG = make_float4(0.f,0.f,0.f,0.f);

    int nb0 = __shfl_sync(FULLM, myidx, 0);
    int nb1 = __shfl_sync(FULLM, myidx, 1);
    float4 qa = __ldg((const float4*)&g_q[nb0*HID + c]);
    float4 qb = __ldg((const float4*)&g_q[nb1*HID + c]);

#pragma unroll
    for (int n = 0; n < KNN; n += 2) {
        float4 h0, h1;
        h0.x = qa.x + P4.x; h0.y = qa.y + P4.y; h0.z = qa.z + P4.z; h0.w = qa.w + P4.w;
        h1.x = qb.x + P4.x; h1.y = qb.y + P4.y; h1.z = qb.z + P4.z; h1.w = qb.w + P4.w;
        float dp0 = fmaf(qa.x,P4.x, fmaf(qa.y,P4.y, fmaf(qa.z,P4.z, qa.w*P4.w)));
        float dp1 = fmaf(qb.x,P4.x, fmaf(qb.y,P4.y, fmaf(qb.z,P4.z, qb.w*P4.w)));
        if (n + 2 < KNN) {
            int na  = __shfl_sync(FULLM, myidx, n+2);
            int nbx = __shfl_sync(FULLM, myidx, n+3);
            qa = __ldg((const float4*)&g_q[na*HID + c]);
            qb = __ldg((const float4*)&g_q[nbx*HID + c]);
        }
#pragma unroll
        for (int off = 16; off; off >>= 1) {
            dp0 += __shfl_xor_sync(FULLM, dp0, off);
            dp1 += __shfl_xor_sync(FULLM, dp1, off);
        }
        float sum0 = __shfl_sync(FULLM, sumn, n);
        float sum1 = __shfl_sync(FULLM, sumn, n+1);
        float bb0  = __shfl_sync(FULLM, bsqn, n);
        float bb1  = __shfl_sync(FULLM, bsqn, n+1);

        float mu0 = sum0 * (1.f/HID);
        float e20 = fmaf(2.0f, dp0, bb0) * (1.f/HID);
        float rs0 = rsqrtf(e20 - mu0*mu0 + 1e-5f);
        float mu1 = sum1 * (1.f/HID);
        float e21 = fmaf(2.0f, dp1, bb1) * (1.f/HID);
        float rs1 = rsqrtf(e21 - mu1*mu1 + 1e-5f);

        accG.x += gelu_fast(fmaf((h0.x - mu0)*rs0, g1v.x, bev.x));
        accG.y += gelu_fast(fmaf((h0.y - mu0)*rs0, g1v.y, bev.y));
        accG.z += gelu_fast(fmaf((h0.z - mu0)*rs0, g1v.z, bev.z));
        accG.w += gelu_fast(fmaf((h0.w - mu0)*rs0, g1v.w, bev.w));
        accG.x += gelu_fast(fmaf((h1.x - mu1)*rs1, g1v.x, bev.x));
        accG.y += gelu_fast(fmaf((h1.y - mu1)*rs1, g1v.y, bev.y));
        accG.z += gelu_fast(fmaf((h1.z - mu1)*rs1, g1v.z, bev.z));
        accG.w += gelu_fast(fmaf((h1.w - mu1)*rs1, g1v.w, bev.w));
    }
    accG.x *= (1.f/KNN); accG.y *= (1.f/KNN);
    accG.z *= (1.f/KNN); accG.w *= (1.f/KNN);

    float m0 = __ldg(&b2[lane]);
    float m1 = __ldg(&b2[lane + 32]);
#pragma unroll
    for (int src = 0; src < 32; src++) {
        float gx = __shfl_sync(FULLM, accG.x, src);
        float gy = __shfl_sync(FULLM, accG.y, src);
        float gz = __shfl_sync(FULLM, accG.z, src);
        float gw = __shfl_sync(FULLM, accG.w, src);
        int k0 = src * 4;
        m0 = fmaf(gx, sW2[(k0+0)*COUT + lane], m0);
        m0 = fmaf(gy, sW2[(k0+1)*COUT + lane], m0);
        m0 = fmaf(gz, sW2[(k0+2)*COUT + lane], m0);
        m0 = fmaf(gw, sW2[(k0+3)*COUT + lane], m0);
        m1 = fmaf(gx, sW2[(k0+0)*COUT + lane + 32], m1);
        m1 = fmaf(gy, sW2[(k0+1)*COUT + lane + 32], m1);
        m1 = fmaf(gz, sW2[(k0+2)*COUT + lane + 32], m1);
        m1 = fmaf(gw, sW2[(k0+3)*COUT + lane + 32], m1);
    }
    g_mid[p*COUT + lane]      = m0;
    g_mid[p*COUT + lane + 32] = m1;
}

// ---------------------------------------------------------------------------
// MLP2 fused: 64 points per block, grid 256.
// ---------------------------------------------------------------------------
#define M2PTS 64
#define SMEM2_FLOATS (COUT*M2PTS + COUT*HID + HID*COUT)  // 20480

__global__ void __launch_bounds__(256, 2) mlp2_kernel(
    const float* __restrict__ Wo1, const float* __restrict__ bo1,
    const float* __restrict__ go,  const float* __restrict__ beo,
    const float* __restrict__ Wo2, const float* __restrict__ bo2,
    float* __restrict__ out)
{
    extern __shared__ float sm[];
    float* sAt  = sm;
    float* sWo1 = sm + COUT*M2PTS;
    float* sH   = sm;                          // aliases sAt+sWo1
    float* sWo2 = sm + COUT*M2PTS + COUT*HID;

    int tid = threadIdx.x;
    int r0  = blockIdx.x * M2PTS;

    for (int e = tid; e < COUT*HID; e += 256) sWo1[e] = Wo1[e];
    for (int e = tid; e < HID*COUT; e += 256) sWo2[e] = Wo2[e];
    for (int e = tid; e < COUT*M2PTS; e += 256) {
        int r = e & (M2PTS-1), k = e >> 6;
        sAt[k*M2PTS + r] = g_mid[(r0 + r)*COUT + k];
    }
    __syncthreads();

    int tx = tid & 15, ty = tid >> 4;

    float acc[4][8];
#pragma unroll
    for (int i = 0; i < 4; i++)
#pragma unroll
        for (int j = 0; j < 8; j++) acc[i][j] = 0.f;

    for (int k = 0; k < COUT; k++) {
        float4 a4 = *(const float4*)&sAt[k*M2PTS + ty*4];
        float4 c0 = *(const float4*)&sWo1[k*HID + tx*8];
        float4 c1 = *(const float4*)&sWo1[k*HID + tx*8 + 4];
        float a[4] = {a4.x,a4.y,a4.z,a4.w};
        float wv[8] = {c0.x,c0.y,c0.z,c0.w,c1.x,c1.y,c1.z,c1.w};
#pragma unroll
        for (int i = 0; i < 4; i++)
#pragma unroll
            for (int j = 0; j < 8; j++)
                acc[i][j] = fmaf(a[i], wv[j], acc[i][j]);
    }

    __syncthreads();

    float b1j[8], gj[8], bej[8];
#pragma unroll
    for (int j = 0; j < 8; j++) {
        int col = tx*8 + j;
        b1j[j] = bo1[col]; gj[j] = go[col]; bej[j] = beo[col];
    }
#pragma unroll
    for (int i = 0; i < 4; i++) {
        float ps = 0.f, ps2 = 0.f;
#pragma unroll
        for (int j = 0; j < 8; j++) {
            float h = acc[i][j] + b1j[j];
            acc[i][j] = h;
            ps += h; ps2 = fmaf(h, h, ps2);
        }
#pragma unroll
        for (int off = 8; off; off >>= 1) {
            ps  += __shfl_xor_sync(FULLM, ps,  off);
            ps2 += __shfl_xor_sync(FULLM, ps2, off);
        }
        float mu  = ps  * (1.f/HID);
        float var = ps2 * (1.f/HID) - mu*mu;
        float rs  = rsqrtf(var + 1e-5f);
        float o[8];
#pragma unroll
        for (int j = 0; j < 8; j++)
            o[j] = gelu_fast(fmaf((acc[i][j] - mu)*rs, gj[j], bej[j]));
        int row = ty*4 + i;
        *(float4*)&sH[row*132 + tx*8]     = make_float4(o[0],o[1],o[2],o[3]);
        *(float4*)&sH[row*132 + tx*8 + 4] = make_float4(o[4],o[5],o[6],o[7]);
    }
    __syncthreads();

    float acc2[4][4];
#pragma unroll
    for (int i = 0; i < 4; i++)
#pragma unroll
        for (int j = 0; j < 4; j++) acc2[i][j] = 0.f;

    for (int k = 0; k < HID; k += 4) {
        float4 w0 = *(const float4*)&sWo2[(k+0)*COUT + tx*4];
        float4 w1 = *(const float4*)&sWo2[(k+1)*COUT + tx*4];
        float4 w2 = *(const float4*)&sWo2[(k+2)*COUT + tx*4];
        float4 w3 = *(const float4*)&sWo2[(k+3)*COUT + tx*4];
#pragma unroll
        for (int i = 0; i < 4; i++) {
            float4 av = *(const float4*)&sH[(ty*4+i)*132 + k];
            acc2[i][0] = fmaf(av.x, w0.x, fmaf(av.y, w1.x, fmaf(av.z, w2.x, fmaf(av.w, w3.x, acc2[i][0]))));
            acc2[i][1] = fmaf(av.x, w0.y, fmaf(av.y, w1.y, fmaf(av.z, w2.y, fmaf(av.w, w3.y, acc2[i][1]))));
            acc2[i][2] = fmaf(av.x, w0.z, fmaf(av.y, w1.z, fmaf(av.z, w2.z, fmaf(av.w, w3.z, acc2[i][2]))));
            acc2[i][3] = fmaf(av.x, w0.w, fmaf(av.y, w1.w, fmaf(av.z, w2.w, fmaf(av.w, w3.w, acc2[i][3]))));
        }
    }

    float b2j[4];
#pragma unroll
    for (int j = 0; j < 4; j++) b2j[j] = bo2[tx*4 + j];
#pragma unroll
    for (int i = 0; i < 4; i++) {
        int row = r0 + ty*4 + i;
#pragma unroll
        for (int j = 0; j < 4; j++)
            out[row*COUT + tx*4 + j] = acc2[i][j] + b2j[j];
    }
}

// ---------------------------------------------------------------------------
extern "C" void kernel_launch(void* const* d_in, const int* in_sizes, int n_in,
                              void* d_out, int out_size) {
    const float* verts = (const float*)d_in[0];
    const float* feat  = (const float*)d_in[1];
    const float* W1    = (const float*)d_in[2];
    const float* b1    = (const float*)d_in[3];
    const float* g1    = (const float*)d_in[4];
    const float* be1   = (const float*)d_in[5];
    const float* W2    = (const float*)d_in[6];
    const float* b2    = (const float*)d_in[7];
    const float* Wo1   = (const float*)d_in[8];
    const float* bo1   = (const float*)d_in[9];
    const float* go    = (const float*)d_in[10];
    const float* beo   = (const float*)d_in[11];
    const float* Wo2   = (const float*)d_in[12];
    const float* bo2   = (const float*)d_in[13];
    float* out = (float*)d_out;

    const int smem2 = SMEM2_FLOATS * 4;   // 81920
    cudaFuncSetAttribute(mlp2_kernel, cudaFuncAttributeMaxDynamicSharedMemorySize, smem2);

    prep_kernel<<<(TOT + 255)/256, 256>>>(verts);
    bin_kernel<<<(TOT + 255)/256, 256>>>();
    scan_kernel<<<BN, 1024>>>();
    scatter_kernel<<<(TOT + 255)/256, 256>>>();
    knn_kernel<<<TOT/8, 256>>>();
    precomp_kernel<<<TOT/8, 256>>>(verts, feat, W1, b1);
    edge_kernel<<<TOT/8, 256>>>(g1, be1, W2, b2);
    mlp2_kernel<<<TOT/M2PTS, 256, smem2>>>(Wo1, bo1, go, beo, Wo2, bo2, out);
}

// round 14
// speedup vs baseline: 1.1356x; 1.0099x over previous
#include <cuda_runtime.h>
#include <math.h>

#define BN   2
#define NPTS 8192
#define KNN  16
#define CIN  32
#define EIN  67      // 32 + 32 + 3
#define HID  128
#define COUT 64
#define TOT  (BN*NPTS)
#define FULLM 0xffffffffu
#define FMAX  3.402823466e38f

// (x,y)-cell sort for KNN
#define NBX   48
#define NBY   48
#define CELLS (NBX*NBY)          // 2304 per batch
#define XMIN  (-4.65f)
#define XSPAN 9.3f
#define BWX   (XSPAN/NBX)
#define INVBWX (NBX/XSPAN)
#define BWY   (XSPAN/NBY)
#define INVBWY (NBY/XSPAN)
#define WIN0  1                  // initial half-window in cells (3x3)

// Scratch (no allocations allowed)
__device__ int    g_idx[TOT*KNN];
__device__ float  g_mid[TOT*COUT];
__device__ float4 g_vert4[TOT];
__device__ float  g_q[TOT*HID];
__device__ float  g_p[TOT*HID];
__device__ float4 g_stat[TOT];
__device__ int    g_ccnt[BN][CELLS];
__device__ int    g_cstart[BN][CELLS+1];
__device__ int    g_ccur[BN][CELLS];
__device__ float4 g_sx4[TOT];              // cell-sorted points
__device__ int    g_ssid[TOT];             // sorted -> original GLOBAL index

// ---------------------------------------------------------------------------
__global__ void prep_kernel(const float* __restrict__ verts) {
    int i = blockIdx.x * blockDim.x + threadIdx.x;
    if (i < TOT) {
        float x = verts[i*3+0], y = verts[i*3+1], z = verts[i*3+2];
        g_vert4[i] = make_float4(x, y, z, x*x + y*y + z*z);
    }
    if (i < BN*CELLS) ((int*)g_ccnt)[i] = 0;
}

__device__ __forceinline__ int clampi(int v, int lo, int hi) {
    return v < lo ? lo : (v > hi ? hi : v);
}

__global__ void bin_kernel() {
    int i = blockIdx.x * blockDim.x + threadIdx.x;
    if (i >= TOT) return;
    float4 v = g_vert4[i];
    int bx = clampi((int)((v.x - XMIN) * INVBWX), 0, NBX-1);
    int by = clampi((int)((v.y - XMIN) * INVBWY), 0, NBY-1);
    atomicAdd(&g_ccnt[i >> 13][bx*NBY + by], 1);
}

// One block per batch, 1024 threads, 3 cells/thread + block-wide scan.
__global__ void scan_kernel() {
    __shared__ int s[1024];
    int bb = blockIdx.x, t = threadIdx.x;
    int lo = t*3, hi = min(lo+3, CELLS);
    int loc[3]; int sum = 0;
    for (int i = lo; i < hi; i++) { loc[i-lo] = g_ccnt[bb][i]; sum += loc[i-lo]; }
    s[t] = sum;
    __syncthreads();
    for (int d = 1; d < 1024; d <<= 1) {
        int u = (t >= d) ? s[t-d] : 0;
        __syncthreads();
        s[t] += u;
        __syncthreads();
    }
    int run = s[t] - sum;
    for (int i = lo; i < hi; i++) {
        g_cstart[bb][i] = run;
        g_ccur[bb][i]   = run;
        run += loc[i-lo];
    }
    if (t == 1023) g_cstart[bb][CELLS] = NPTS;
}

__global__ void scatter_kernel() {
    int i = blockIdx.x * blockDim.x + threadIdx.x;
    if (i >= TOT) return;
    float4 v = g_vert4[i];
    int bb = i >> 13;
    int bx = clampi((int)((v.x - XMIN) * INVBWX), 0, NBX-1);
    int by = clampi((int)((v.y - XMIN) * INVBWY), 0, NBY-1);
    int slot = bb * NPTS + atomicAdd(&g_ccur[bb][bx*NBY + by], 1);
    g_sx4[slot]  = v;
    g_ssid[slot] = i;
}

// ---------------------------------------------------------------------------
// Scan sorted segment [a,b) through the warp's ascending lane-sorted best-32
// queue (batch-frozen threshold; identical distance formula as brute force).
// ---------------------------------------------------------------------------
__device__ __forceinline__ void scan_seg(int a, int b, int sbase, float4 qv,
                                         int lane, float& key, int& idx) {
    for (int i = a; i < b; i += 32) {
        int j = i + lane;
        float d = FMAX;
        if (j < b) {
            float4 c = __ldg(&g_sx4[sbase + j]);
            float dot = fmaf(qv.x, c.x, fmaf(qv.y, c.y, qv.z*c.z));
            d = fmaf(-2.0f, dot, qv.w + c.w);
        }
        float thb = __shfl_sync(FULLM, key, 15);
        unsigned mask = __ballot_sync(FULLM, d < thb);
        while (mask) {
            int src = __ffs(mask) - 1;
            mask &= mask - 1;
            float v  = __shfl_sync(FULLM, d, src);
            int   vi = i + src;
            float pk = __shfl_up_sync(FULLM, key, 1);
            int   pi = __shfl_up_sync(FULLM, idx, 1);
            if (v < key) {
                if (lane > 0 && v < pk) { key = pk; idx = pi; }
                else                    { key = v;  idx = vi; }
            }
        }
    }
}

// ---------------------------------------------------------------------------
// KNN: warp per query over (x,y)-sorted cells, CSR staged in SMEM.
// Queue warm-started with a BITONIC SORT of the first 32 candidates from the
// center column (closest points -> tight threshold immediately, and 15
// parallel compare-exchanges replace 32 serial inserts).
// ---------------------------------------------------------------------------
__global__ void __launch_bounds__(256) knn_kernel() {
    __shared__ int scs[CELLS+1];     // 9.2KB
    int tid  = threadIdx.x;
    int lane = tid & 31;
    int w    = tid >> 5;
    int gq   = blockIdx.x * 8 + w;
    int bb   = gq >> 13;
    int sbase = bb * NPTS;

    for (int i = tid; i <= CELLS; i += 256) scs[i] = g_cstart[bb][i];
    __syncthreads();

    float4 qv = g_vert4[gq];
    int bx0 = clampi((int)((qv.x - XMIN) * INVBWX), 0, NBX-1);
    int by0 = clampi((int)((qv.y - XMIN) * INVBWY), 0, NBY-1);

    int xlo = max(0, bx0 - WIN0), xhi = min(NBX-1, bx0 + WIN0);
    int ylo = max(0, by0 - WIN0), yhi = min(NBY-1, by0 + WIN0);

    // --- bitonic warm-start from the center column's first 32 candidates ---
    int a0 = scs[bx0*NBY + ylo], b0 = scs[bx0*NBY + yhi + 1];
    float key; int idx;
    {
        float d = FMAX; int vi = 0;
        int j = a0 + lane;
        if (j < b0) {
            float4 c = __ldg(&g_sx4[sbase + j]);
            float dot = fmaf(qv.x, c.x, fmaf(qv.y, c.y, qv.z*c.z));
            d = fmaf(-2.0f, dot, qv.w + c.w);
            vi = j;
        }
#pragma unroll
        for (int k = 2; k <= 32; k <<= 1) {
#pragma unroll
            for (int s = k >> 1; s > 0; s >>= 1) {
                int partner = lane ^ s;
                float ok = __shfl_xor_sync(FULLM, d,  s);
                int   oi = __shfl_xor_sync(FULLM, vi, s);
                bool dir = ((lane & k) == 0);
                bool otherLess = (ok < d) || (ok == d && partner < lane);
                bool lower = ((lane & s) == 0);
                bool take = (lower == dir) ? otherLess : !otherLess;
                if (take) { d = ok; vi = oi; }
            }
        }
        key = d; idx = vi;
    }
    // rest of center column, then the other initial columns
    scan_seg(min(a0 + 32, b0), b0, sbase, qv, lane, key, idx);
    for (int bx = xlo; bx <= xhi; bx++)
        if (bx != bx0)
            scan_seg(scs[bx*NBY + ylo], scs[bx*NBY + yhi + 1], sbase, qv, lane, key, idx);

    for (;;) {
        float gxl = (xlo == 0)       ? FMAX : qv.x - (XMIN + xlo * BWX);
        float gxh = (xhi == NBX - 1) ? FMAX : (XMIN + (xhi + 1) * BWX) - qv.x;
        float gyl = (ylo == 0)       ? FMAX : qv.y - (XMIN + ylo * BWY);
        float gyh = (yhi == NBY - 1) ? FMAX : (XMIN + (yhi + 1) * BWY) - qv.y;
        float bnd = fminf(fminf(gxl, gxh), fminf(gyl, gyh));
        if (bnd > 1e37f) break;                       // everything scanned
        float th = __shfl_sync(FULLM, key, 15);
        if (th <= bnd * bnd) break;                   // exact stop bound
        if (gxl <= gxh && gxl <= gyl && gxl <= gyh) {
            xlo--;
            scan_seg(scs[xlo*NBY + ylo], scs[xlo*NBY + yhi + 1], sbase, qv, lane, key, idx);
        } else if (gxh <= gyl && gxh <= gyh) {
            xhi++;
            scan_seg(scs[xhi*NBY + ylo], scs[xhi*NBY + yhi + 1], sbase, qv, lane, key, idx);
        } else if (gyl <= gyh) {
            ylo--;
            for (int bx = xlo; bx <= xhi; bx++)
                scan_seg(scs[bx*NBY + ylo], scs[bx*NBY + ylo + 1], sbase, qv, lane, key, idx);
        } else {
            yhi++;
            for (int bx = xlo; bx <= xhi; bx++)
                scan_seg(scs[bx*NBY + yhi], scs[bx*NBY + yhi + 1], sbase, qv, lane, key, idx);
        }
    }

    if (lane < KNN) g_idx[gq*KNN + lane] = g_ssid[sbase + idx];
}

// ---------------------------------------------------------------------------
// Precompute Q[n], P[n] and their channel sums / sum-of-squares.
// ---------------------------------------------------------------------------
__global__ void __launch_bounds__(256) precomp_kernel(
    const float* __restrict__ verts, const float* __restrict__ feat,
    const float* __restrict__ W1, const float* __restrict__ b1)
{
    __shared__ float sW1[EIN*HID];   // 34.3KB
    int tid = threadIdx.x, lane = tid & 31, w = tid >> 5;
    for (int e = tid; e < EIN*HID; e += 256) sW1[e] = W1[e];
    __syncthreads();

    int p = blockIdx.x * 8 + w;
    float4 f4 = make_float4(0.f,0.f,0.f,0.f);
    if (lane < 8) f4 = *(const float4*)&feat[p*CIN + lane*4];
    float vx = verts[p*3+0], vy = verts[p*3+1], vz = verts[p*3+2];

    int c = lane*4;
    float4 q  = make_float4(0.f,0.f,0.f,0.f);
    float4 pp = *(const float4*)&b1[c];

#pragma unroll
    for (int src = 0; src < 8; src++) {
        float fx = __shfl_sync(FULLM, f4.x, src);
        float fy = __shfl_sync(FULLM, f4.y, src);
        float fz = __shfl_sync(FULLM, f4.z, src);
        float fw = __shfl_sync(FULLM, f4.w, src);
        float fv[4] = {fx, fy, fz, fw};
        int k0 = src*4;
#pragma unroll
        for (int kk = 0; kk < 4; kk++) {
            int k = k0 + kk;
            float4 wa = *(const float4*)&sW1[k*HID + c];
            float4 wb = *(const float4*)&sW1[(CIN + k)*HID + c];
            q.x  = fmaf(fv[kk], wa.x, q.x);  q.y  = fmaf(fv[kk], wa.y, q.y);
            q.z  = fmaf(fv[kk], wa.z, q.z);  q.w  = fmaf(fv[kk], wa.w, q.w);
            pp.x = fmaf(fv[kk], wb.x, pp.x); pp.y = fmaf(fv[kk], wb.y, pp.y);
            pp.z = fmaf(fv[kk], wb.z, pp.z); pp.w = fmaf(fv[kk], wb.w, pp.w);
        }
    }
    float vv[3] = {vx, vy, vz};
#pragma unroll
    for (int k = 0; k < 3; k++) {
        float4 wc = *(const float4*)&sW1[(2*CIN + k)*HID + c];
        q.x  = fmaf(vv[k],  wc.x, q.x);  q.y  = fmaf(vv[k],  wc.y, q.y);
        q.z  = fmaf(vv[k],  wc.z, q.z);  q.w  = fmaf(vv[k],  wc.w, q.w);
        pp.x = fmaf(-vv[k], wc.x, pp.x); pp.y = fmaf(-vv[k], wc.y, pp.y);
        pp.z = fmaf(-vv[k], wc.z, pp.z); pp.w = fmaf(-vv[k], wc.w, pp.w);
    }
    *(float4*)&g_q[p*HID + c] = q;
    *(float4*)&g_p[p*HID + c] = pp;

    float sq  = (q.x + q.y) + (q.z + q.w);
    float sq2 = fmaf(q.x,q.x, fmaf(q.y,q.y, fmaf(q.z,q.z, q.w*q.w)));
    float sp  = (pp.x + pp.y) + (pp.z + pp.w);
    float sp2 = fmaf(pp.x,pp.x, fmaf(pp.y,pp.y, fmaf(pp.z,pp.z, pp.w*pp.w)));
#pragma unroll
    for (int off = 16; off; off >>= 1) {
        sq  += __shfl_xor_sync(FULLM, sq,  off);
        sq2 += __shfl_xor_sync(FULLM, sq2, off);
        sp  += __shfl_xor_sync(FULLM, sp,  off);
        sp2 += __shfl_xor_sync(FULLM, sp2, off);
    }
    if (lane == 0) g_stat[p] = make_float4(sq, sq2, sp, sp2);
}

// ---------------------------------------------------------------------------
__device__ __forceinline__ float gelu_fast(float x) {
    float z2 = 1.5957691216057308f * fmaf(0.044715f * x * x, x, x);
    float e  = __expf(z2);
    float r  = __fdividef(1.0f, e + 1.0f);
    return x - x * r;
}

// ---------------------------------------------------------------------------
// Edge kernel: warp per point, FOUR neighbors per iteration (4 independent
// butterfly chains in flight). LN stats via precomputed sums.
// ---------------------------------------------------------------------------
__global__ void __launch_bounds__(256) edge_kernel(
    const float* __restrict__ g1, const float* __restrict__ be1,
    const float* __restrict__ W2, const float* __restrict__ b2)
{
    __shared__ float sW2[HID*COUT];   // 32KB
    int tid = threadIdx.x, lane = tid & 31, w = tid >> 5;
    for (int e = tid; e < HID*COUT; e += 256) sW2[e] = W2[e];
    __syncthreads();

    int p = blockIdx.x * 8 + w;
    int myidx = (lane < KNN) ? g_idx[p*KNN + lane] : 0;
    int c = lane * 4;

    float4 P4  = *(const float4*)&g_p[p*HID + c];
    float4 g1v = *(const float4*)&g1[c];
    float4 bev = *(const float4*)&be1[c];
    float4 stP = g_stat[p];
    float4 stN = __ldg(&g_stat[myidx]);
    float sumn = stN.x + stP.z;
    float bsqn = stN.y + stP.w;

    float4 accG = make_float4(0.f,0.f,0.f,0.f);

    float4 qn[4];
#pragma unroll
    for (int r = 0; r < 4; r++) {
        int nb = __shfl_sync(FULLM, myidx, r);
        qn[r] = __ldg((const float4*)&g_q[nb*HID + c]);
    }

#pragma unroll
    for (int n = 0; n < KNN; n += 4) {
        float4 h[4];
        float dp[4];
#pragma unroll
        for (int r = 0; r < 4; r++) {
            h[r].x = qn[r].x + P4.x; h[r].y = qn[r].y + P4.y;
            h[r].z = qn[r].z + P4.z; h[r].w = qn[r].w + P4.w;
            dp[r] = fmaf(qn[r].x,P4.x, fmaf(qn[r].y,P4.y, fmaf(qn[r].z,P4.z, qn[r].w*P4.w)));
        }
        if (n + 4 < KNN) {
#pragma unroll
            for (int r = 0; r < 4; r++) {
                int nb = __shfl_sync(FULLM, myidx, n + 4 + r);
                qn[r] = __ldg((const float4*)&g_q[nb*HID + c]);
            }
        }
#pragma unroll
        for (int off = 16; off; off >>= 1) {
#pragma unroll
            for (int r = 0; r < 4; r++)
                dp[r] += __shfl_xor_sync(FULLM, dp[r], off);
        }
#pragma unroll
        for (int r = 0; r < 4; r++) {
            float sum = __shfl_sync(FULLM, sumn, n + r);
            float bsq = __shfl_sync(FULLM, bsqn, n + r);
            float mu  = sum * (1.f/HID);
            float e2  = fmaf(2.0f, dp[r], bsq) * (1.f/HID);
            float rs  = rsqrtf(e2 - mu*mu + 1e-5f);
            accG.x += gelu_fast(fmaf((h[r].x - mu)*rs, g1v.x, bev.x));
            accG.y += gelu_fast(fmaf((h[r].y - mu)*rs, g1v.y, bev.y));
            accG.z += gelu_fast(fmaf((h[r].z - mu)*rs, g1v.z, bev.z));
            accG.w += gelu_fast(fmaf((h[r].w - mu)*rs, g1v.w, bev.w));
        }
    }
    accG.x *= (1.f/KNN); accG.y *= (1.f/KNN);
    accG.z *= (1.f/KNN); accG.w *= (1.f/KNN);

    float m0 = __ldg(&b2[lane]);
    float m1 = __ldg(&b2[lane + 32]);
#pragma unroll
    for (int src = 0; src < 32; src++) {
        float gx = __shfl_sync(FULLM, accG.x, src);
        float gy = __shfl_sync(FULLM, accG.y, src);
        float gz = __shfl_sync(FULLM, accG.z, src);
        float gw = __shfl_sync(FULLM, accG.w, src);
        int k0 = src * 4;
        m0 = fmaf(gx, sW2[(k0+0)*COUT + lane], m0);
        m0 = fmaf(gy, sW2[(k0+1)*COUT + lane], m0);
        m0 = fmaf(gz, sW2[(k0+2)*COUT + lane], m0);
        m0 = fmaf(gw, sW2[(k0+3)*COUT + lane], m0);
        m1 = fmaf(gx, sW2[(k0+0)*COUT + lane + 32], m1);
        m1 = fmaf(gy, sW2[(k0+1)*COUT + lane + 32], m1);
        m1 = fmaf(gz, sW2[(k0+2)*COUT + lane + 32], m1);
        m1 = fmaf(gw, sW2[(k0+3)*COUT + lane + 32], m1);
    }
    g_mid[p*COUT + lane]      = m0;
    g_mid[p*COUT + lane + 32] = m1;
}

// ---------------------------------------------------------------------------
// MLP2 fused: 64 points per block, grid 256.
// ---------------------------------------------------------------------------
#define M2PTS 64
#define SMEM2_FLOATS (COUT*M2PTS + COUT*HID + HID*COUT)  // 20480

__global__ void __launch_bounds__(256, 2) mlp2_kernel(
    const float* __restrict__ Wo1, const float* __restrict__ bo1,
    const float* __restrict__ go,  const float* __restrict__ beo,
    const float* __restrict__ Wo2, const float* __restrict__ bo2,
    float* __restrict__ out)
{
    extern __shared__ float sm[];
    float* sAt  = sm;
    float* sWo1 = sm + COUT*M2PTS;
    float* sH   = sm;                          // aliases sAt+sWo1
    float* sWo2 = sm + COUT*M2PTS + COUT*HID;

    int tid = threadIdx.x;
    int r0  = blockIdx.x * M2PTS;

    for (int e = tid; e < COUT*HID; e += 256) sWo1[e] = Wo1[e];
    for (int e = tid; e < HID*COUT; e += 256) sWo2[e] = Wo2[e];
    for (int e = tid; e < COUT*M2PTS; e += 256) {
        int r = e & (M2PTS-1), k = e >> 6;
        sAt[k*M2PTS + r] = g_mid[(r0 + r)*COUT + k];
    }
    __syncthreads();

    int tx = tid & 15, ty = tid >> 4;

    float acc[4][8];
#pragma unroll
    for (int i = 0; i < 4; i++)
#pragma unroll
        for (int j = 0; j < 8; j++) acc[i][j] = 0.f;

    for (int k = 0; k < COUT; k++) {
        float4 a4 = *(const float4*)&sAt[k*M2PTS + ty*4];
        float4 c0 = *(const float4*)&sWo1[k*HID + tx*8];
        float4 c1 = *(const float4*)&sWo1[k*HID + tx*8 + 4];
        float a[4] = {a4.x,a4.y,a4.z,a4.w};
        float wv[8] = {c0.x,c0.y,c0.z,c0.w,c1.x,c1.y,c1.z,c1.w};
#pragma unroll
        for (int i = 0; i < 4; i++)
#pragma unroll
            for (int j = 0; j < 8; j++)
                acc[i][j] = fmaf(a[i], wv[j], acc[i][j]);
    }

    __syncthreads();

    float b1j[8], gj[8], bej[8];
#pragma unroll
    for (int j = 0; j < 8; j++) {
        int col = tx*8 + j;
        b1j[j] = bo1[col]; gj[j] = go[col]; bej[j] = beo[col];
    }
#pragma unroll
    for (int i = 0; i < 4; i++) {
        float ps = 0.f, ps2 = 0.f;
#pragma unroll
        for (int j = 0; j < 8; j++) {
            float h = acc[i][j] + b1j[j];
            acc[i][j] = h;
            ps += h; ps2 = fmaf(h, h, ps2);
        }
#pragma unroll
        for (int off = 8; off; off >>= 1) {
            ps  += __shfl_xor_sync(FULLM, ps,  off);
            ps2 += __shfl_xor_sync(FULLM, ps2, off);
        }
        float mu  = ps  * (1.f/HID);
        float var = ps2 * (1.f/HID) - mu*mu;
        float rs  = rsqrtf(var + 1e-5f);
        float o[8];
#pragma unroll
        for (int j = 0; j < 8; j++)
            o[j] = gelu_fast(fmaf((acc[i][j] - mu)*rs, gj[j], bej[j]));
        int row = ty*4 + i;
        *(float4*)&sH[row*132 + tx*8]     = make_float4(o[0],o[1],o[2],o[3]);
        *(float4*)&sH[row*132 + tx*8 + 4] = make_float4(o[4],o[5],o[6],o[7]);
    }
    __syncthreads();

    float acc2[4][4];
#pragma unroll
    for (int i = 0; i < 4; i++)
#pragma unroll
        for (int j = 0; j < 4; j++) acc2[i][j] = 0.f;

    for (int k = 0; k < HID; k += 4) {
        float4 w0 = *(const float4*)&sWo2[(k+0)*COUT + tx*4];
        float4 w1 = *(const float4*)&sWo2[(k+1)*COUT + tx*4];
        float4 w2 = *(const float4*)&sWo2[(k+2)*COUT + tx*4];
        float4 w3 = *(const float4*)&sWo2[(k+3)*COUT + tx*4];
#pragma unroll
        for (int i = 0; i < 4; i++) {
            float4 av = *(const float4*)&sH[(ty*4+i)*132 + k];
            acc2[i][0] = fmaf(av.x, w0.x, fmaf(av.y, w1.x, fmaf(av.z, w2.x, fmaf(av.w, w3.x, acc2[i][0]))));
            acc2[i][1] = fmaf(av.x, w0.y, fmaf(av.y, w1.y, fmaf(av.z, w2.y, fmaf(av.w, w3.y, acc2[i][1]))));
            acc2[i][2] = fmaf(av.x, w0.z, fmaf(av.y, w1.z, fmaf(av.z, w2.z, fmaf(av.w, w3.z, acc2[i][2]))));
            acc2[i][3] = fmaf(av.x, w0.w, fmaf(av.y, w1.w, fmaf(av.z, w2.w, fmaf(av.w, w3.w, acc2[i][3]))));
        }
    }

    float b2j[4];
#pragma unroll
    for (int j = 0; j < 4; j++) b2j[j] = bo2[tx*4 + j];
#pragma unroll
    for (int i = 0; i < 4; i++) {
        int row = r0 + ty*4 + i;
#pragma unroll
        for (int j = 0; j < 4; j++)
            out[row*COUT + tx*4 + j] = acc2[i][j] + b2j[j];
    }
}

// ---------------------------------------------------------------------------
extern "C" void kernel_launch(void* const* d_in, const int* in_sizes, int n_in,
                              void* d_out, int out_size) {
    const float* verts = (const float*)d_in[0];
    const float* feat  = (const float*)d_in[1];
    const float* W1    = (const float*)d_in[2];
    const float* b1    = (const float*)d_in[3];
    const float* g1    = (const float*)d_in[4];
    const float* be1   = (const float*)d_in[5];
    const float* W2    = (const float*)d_in[6];
    const float* b2    = (const float*)d_in[7];
    const float* Wo1   = (const float*)d_in[8];
    const float* bo1   = (const float*)d_in[9];
    const float* go    = (const float*)d_in[10];
    const float* beo   = (const float*)d_in[11];
    const float* Wo2   = (const float*)d_in[12];
    const float* bo2   = (const float*)d_in[13];
    float* out = (float*)d_out;

    const int smem2 = SMEM2_FLOATS * 4;   // 81920
    cudaFuncSetAttribute(mlp2_kernel, cudaFuncAttributeMaxDynamicSharedMemorySize, smem2);

    prep_kernel<<<(TOT + 255)/256, 256>>>(verts);
    bin_kernel<<<(TOT + 255)/256, 256>>>();
    scan_kernel<<<BN, 1024>>>();
    scatter_kernel<<<(TOT + 255)/256, 256>>>();
    knn_kernel<<<TOT/8, 256>>>();
    precomp_kernel<<<TOT/8, 256>>>(verts, feat, W1, b1);
    edge_kernel<<<TOT/8, 256>>>(g1, be1, W2, b2);
    mlp2_kernel<<<TOT/M2PTS, 256, smem2>>>(Wo1, bo1, go, beo, Wo2, bo2, out);
}

// round 15
// speedup vs baseline: 1.3463x; 1.1855x over previous
#include <cuda_runtime.h>
#include <math.h>

#define BN   2
#define NPTS 8192
#define KNN  16
#define CIN  32
#define EIN  67      // 32 + 32 + 3
#define HID  128
#define COUT 64
#define TOT  (BN*NPTS)
#define FULLM 0xffffffffu
#define FMAX  3.402823466e38f

// 3-D cell sort for KNN: 16^3 cells, z contiguous (lex order bx,by,bz)
#define NC3    16
#define CELLS3 (NC3*NC3*NC3)     // 4096 per batch
#define XMIN  (-4.65f)
#define XSPAN 9.3f
#define BW3   (XSPAN/NC3)        // 0.58125
#define INVBW3 (NC3/XSPAN)

// Scratch (no allocations allowed)
__device__ int    g_idx[TOT*KNN];
__device__ float  g_mid[TOT*COUT];
__device__ float4 g_vert4[TOT];
__device__ float  g_q[TOT*HID];
__device__ float  g_p[TOT*HID];
__device__ float4 g_stat[TOT];
__device__ int    g_ccnt[BN][CELLS3];
__device__ int    g_cstart[BN][CELLS3+1];
__device__ int    g_ccur[BN][CELLS3];
__device__ float4 g_sx4[TOT];              // cell-sorted points
__device__ int    g_ssid[TOT];             // sorted -> original GLOBAL index

// ---------------------------------------------------------------------------
__global__ void prep_kernel(const float* __restrict__ verts) {
    int i = blockIdx.x * blockDim.x + threadIdx.x;
    if (i < TOT) {
        float x = verts[i*3+0], y = verts[i*3+1], z = verts[i*3+2];
        g_vert4[i] = make_float4(x, y, z, x*x + y*y + z*z);
    }
    if (i < BN*CELLS3) ((int*)g_ccnt)[i] = 0;
}

__device__ __forceinline__ int clampi(int v, int lo, int hi) {
    return v < lo ? lo : (v > hi ? hi : v);
}

__global__ void bin_kernel() {
    int i = blockIdx.x * blockDim.x + threadIdx.x;
    if (i >= TOT) return;
    float4 v = g_vert4[i];
    int bx = clampi((int)((v.x - XMIN) * INVBW3), 0, NC3-1);
    int by = clampi((int)((v.y - XMIN) * INVBW3), 0, NC3-1);
    int bz = clampi((int)((v.z - XMIN) * INVBW3), 0, NC3-1);
    atomicAdd(&g_ccnt[i >> 13][(bx*NC3 + by)*NC3 + bz], 1);
}

// One block per batch, 1024 threads, 4 cells/thread + block-wide scan.
__global__ void scan_kernel() {
    __shared__ int s[1024];
    int bb = blockIdx.x, t = threadIdx.x;
    int lo = t*4;
    int loc[4]; int sum = 0;
#pragma unroll
    for (int k = 0; k < 4; k++) { loc[k] = g_ccnt[bb][lo+k]; sum += loc[k]; }
    s[t] = sum;
    __syncthreads();
    for (int d = 1; d < 1024; d <<= 1) {
        int u = (t >= d) ? s[t-d] : 0;
        __syncthreads();
        s[t] += u;
        __syncthreads();
    }
    int run = s[t] - sum;
#pragma unroll
    for (int k = 0; k < 4; k++) {
        g_cstart[bb][lo+k] = run;
        g_ccur[bb][lo+k]   = run;
        run += loc[k];
    }
    if (t == 1023) g_cstart[bb][CELLS3] = NPTS;
}

__global__ void scatter_kernel() {
    int i = blockIdx.x * blockDim.x + threadIdx.x;
    if (i >= TOT) return;
    float4 v = g_vert4[i];
    int bb = i >> 13;
    int bx = clampi((int)((v.x - XMIN) * INVBW3), 0, NC3-1);
    int by = clampi((int)((v.y - XMIN) * INVBW3), 0, NC3-1);
    int bz = clampi((int)((v.z - XMIN) * INVBW3), 0, NC3-1);
    int slot = bb * NPTS + atomicAdd(&g_ccur[bb][(bx*NC3 + by)*NC3 + bz], 1);
    g_sx4[slot]  = v;
    g_ssid[slot] = i;
}

// ---------------------------------------------------------------------------
// Scan sorted segment [a,b) through the warp's ascending lane-sorted best-32
// queue (batch-frozen threshold; identical distance formula as brute force).
// ---------------------------------------------------------------------------
__device__ __forceinline__ void scan_seg(int a, int b, int sbase, float4 qv,
                                         int lane, float& key, int& idx) {
    for (int i = a; i < b; i += 32) {
        int j = i + lane;
        float d = FMAX;
        if (j < b) {
            float4 c = __ldg(&g_sx4[sbase + j]);
            float dot = fmaf(qv.x, c.x, fmaf(qv.y, c.y, qv.z*c.z));
            d = fmaf(-2.0f, dot, qv.w + c.w);
        }
        float thb = __shfl_sync(FULLM, key, 15);
        unsigned mask = __ballot_sync(FULLM, d < thb);
        while (mask) {
            int src = __ffs(mask) - 1;
            mask &= mask - 1;
            float v  = __shfl_sync(FULLM, d, src);
            int   vi = i + src;
            float pk = __shfl_up_sync(FULLM, key, 1);
            int   pi = __shfl_up_sync(FULLM, idx, 1);
            if (v < key) {
                if (lane > 0 && v < pk) { key = pk; idx = pi; }
                else                    { key = v;  idx = vi; }
            }
        }
    }
}

// ---------------------------------------------------------------------------
// KNN: warp per query over 3-D sorted cells, CSR in SMEM. Box window with
// SIX-face gap bound (z pruning finally works). Bitonic warm-start on the
// center column's first 32 candidates.
// ---------------------------------------------------------------------------
__global__ void __launch_bounds__(256) knn_kernel() {
    __shared__ int scs[CELLS3+1];    // 16.4KB
    int tid  = threadIdx.x;
    int lane = tid & 31;
    int w    = tid >> 5;
    int gq   = blockIdx.x * 8 + w;
    int bb   = gq >> 13;
    int sbase = bb * NPTS;

    for (int i = tid; i <= CELLS3; i += 256) scs[i] = g_cstart[bb][i];
    __syncthreads();

    float4 qv = g_vert4[gq];
    int bx0 = clampi((int)((qv.x - XMIN) * INVBW3), 0, NC3-1);
    int by0 = clampi((int)((qv.y - XMIN) * INVBW3), 0, NC3-1);
    int bz0 = clampi((int)((qv.z - XMIN) * INVBW3), 0, NC3-1);

    int xlo = max(0, bx0-1), xhi = min(NC3-1, bx0+1);
    int ylo = max(0, by0-1), yhi = min(NC3-1, by0+1);
    int zlo = max(0, bz0-1), zhi = min(NC3-1, bz0+1);

    // --- bitonic warm-start: first 32 of the center (bx0,by0) z-segment ---
    int cb0 = (bx0*NC3 + by0)*NC3;
    int a0 = scs[cb0 + zlo], b0 = scs[cb0 + zhi + 1];
    float key; int idx;
    {
        float d = FMAX; int vi = 0;
        int j = a0 + lane;
        if (j < b0) {
            float4 c = __ldg(&g_sx4[sbase + j]);
            float dot = fmaf(qv.x, c.x, fmaf(qv.y, c.y, qv.z*c.z));
            d = fmaf(-2.0f, dot, qv.w + c.w);
            vi = j;
        }
#pragma unroll
        for (int k = 2; k <= 32; k <<= 1) {
#pragma unroll
            for (int s = k >> 1; s > 0; s >>= 1) {
                int partner = lane ^ s;
                float ok = __shfl_xor_sync(FULLM, d,  s);
                int   oi = __shfl_xor_sync(FULLM, vi, s);
                bool dir = ((lane & k) == 0);
                bool otherLess = (ok < d) || (ok == d && partner < lane);
                bool lower = ((lane & s) == 0);
                bool take = (lower == dir) ? otherLess : !otherLess;
                if (take) { d = ok; vi = oi; }
            }
        }
        key = d; idx = vi;
    }
    scan_seg(min(a0 + 32, b0), b0, sbase, qv, lane, key, idx);
    // other initial columns
    for (int bx = xlo; bx <= xhi; bx++)
        for (int by = ylo; by <= yhi; by++) {
            if (bx == bx0 && by == by0) continue;
            int cb = (bx*NC3 + by)*NC3;
            scan_seg(scs[cb + zlo], scs[cb + zhi + 1], sbase, qv, lane, key, idx);
        }

    for (;;) {
        float gxl = (xlo == 0)       ? FMAX : qv.x - (XMIN + xlo * BW3);
        float gxh = (xhi == NC3 - 1) ? FMAX : (XMIN + (xhi + 1) * BW3) - qv.x;
        float gyl = (ylo == 0)       ? FMAX : qv.y - (XMIN + ylo * BW3);
        float gyh = (yhi == NC3 - 1) ? FMAX : (XMIN + (yhi + 1) * BW3) - qv.y;
        float gzl = (zlo == 0)       ? FMAX : qv.z - (XMIN + zlo * BW3);
        float gzh = (zhi == NC3 - 1) ? FMAX : (XMIN + (zhi + 1) * BW3) - qv.z;
        float bnd = fminf(fminf(fminf(gxl, gxh), fminf(gyl, gyh)), fminf(gzl, gzh));
        if (bnd > 1e37f) break;                       // everything scanned
        float th = __shfl_sync(FULLM, key, 15);
        if (th <= bnd * bnd) break;                   // exact 3-D stop bound

        if (gxl <= gxh && gxl <= gyl && gxl <= gyh && gxl <= gzl && gxl <= gzh) {
            xlo--;
            for (int by = ylo; by <= yhi; by++) {
                int cb = (xlo*NC3 + by)*NC3;
                scan_seg(scs[cb + zlo], scs[cb + zhi + 1], sbase, qv, lane, key, idx);
            }
        } else if (gxh <= gyl && gxh <= gyh && gxh <= gzl && gxh <= gzh) {
            xhi++;
            for (int by = ylo; by <= yhi; by++) {
                int cb = (xhi*NC3 + by)*NC3;
                scan_seg(scs[cb + zlo], scs[cb + zhi + 1], sbase, qv, lane, key, idx);
            }
        } else if (gyl <= gyh && gyl <= gzl && gyl <= gzh) {
            ylo--;
            for (int bx = xlo; bx <= xhi; bx++) {
                int cb = (bx*NC3 + ylo)*NC3;
                scan_seg(scs[cb + zlo], scs[cb + zhi + 1], sbase, qv, lane, key, idx);
            }
        } else if (gyh <= gzl && gyh <= gzh) {
            yhi++;
            for (int bx = xlo; bx <= xhi; bx++) {
                int cb = (bx*NC3 + yhi)*NC3;
                scan_seg(scs[cb + zlo], scs[cb + zhi + 1], sbase, qv, lane, key, idx);
            }
        } else if (gzl <= gzh) {
            zlo--;
            for (int bx = xlo; bx <= xhi; bx++)
                for (int by = ylo; by <= yhi; by++) {
                    int cb = (bx*NC3 + by)*NC3;
                    scan_seg(scs[cb + zlo], scs[cb + zlo + 1], sbase, qv, lane, key, idx);
                }
        } else {
            zhi++;
            for (int bx = xlo; bx <= xhi; bx++)
                for (int by = ylo; by <= yhi; by++) {
                    int cb = (bx*NC3 + by)*NC3;
                    scan_seg(scs[cb + zhi], scs[cb + zhi + 1], sbase, qv, lane, key, idx);
                }
        }
    }

    if (lane < KNN) g_idx[gq*KNN + lane] = g_ssid[sbase + idx];
}

// ---------------------------------------------------------------------------
// Precompute Q[n], P[n] and their channel sums / sum-of-squares.
// ---------------------------------------------------------------------------
__global__ void __launch_bounds__(256) precomp_kernel(
    const float* __restrict__ verts, const float* __restrict__ feat,
    const float* __restrict__ W1, const float* __restrict__ b1)
{
    __shared__ float sW1[EIN*HID];   // 34.3KB
    int tid = threadIdx.x, lane = tid & 31, w = tid >> 5;
    for (int e = tid; e < EIN*HID; e += 256) sW1[e] = W1[e];
    __syncthreads();

    int p = blockIdx.x * 8 + w;
    float4 f4 = make_float4(0.f,0.f,0.f,0.f);
    if (lane < 8) f4 = *(const float4*)&feat[p*CIN + lane*4];
    float vx = verts[p*3+0], vy = verts[p*3+1], vz = verts[p*3+2];

    int c = lane*4;
    float4 q  = make_float4(0.f,0.f,0.f,0.f);
    float4 pp = *(const float4*)&b1[c];

#pragma unroll
    for (int src = 0; src < 8; src++) {
        float fx = __shfl_sync(FULLM, f4.x, src);
        float fy = __shfl_sync(FULLM, f4.y, src);
        float fz = __shfl_sync(FULLM, f4.z, src);
        float fw = __shfl_sync(FULLM, f4.w, src);
        float fv[4] = {fx, fy, fz, fw};
        int k0 = src*4;
#pragma unroll
        for (int kk = 0; kk < 4; kk++) {
            int k = k0 + kk;
            float4 wa = *(const float4*)&sW1[k*HID + c];
            float4 wb = *(const float4*)&sW1[(CIN + k)*HID + c];
            q.x  = fmaf(fv[kk], wa.x, q.x);  q.y  = fmaf(fv[kk], wa.y, q.y);
            q.z  = fmaf(fv[kk], wa.z, q.z);  q.w  = fmaf(fv[kk], wa.w, q.w);
            pp.x = fmaf(fv[kk], wb.x, pp.x); pp.y = fmaf(fv[kk], wb.y, pp.y);
            pp.z = fmaf(fv[kk], wb.z, pp.z); pp.w = fmaf(fv[kk], wb.w, pp.w);
        }
    }
    float vv[3] = {vx, vy, vz};
#pragma unroll
    for (int k = 0; k < 3; k++) {
        float4 wc = *(const float4*)&sW1[(2*CIN + k)*HID + c];
        q.x  = fmaf(vv[k],  wc.x, q.x);  q.y  = fmaf(vv[k],  wc.y, q.y);
        q.z  = fmaf(vv[k],  wc.z, q.z);  q.w  = fmaf(vv[k],  wc.w, q.w);
        pp.x = fmaf(-vv[k], wc.x, pp.x); pp.y = fmaf(-vv[k], wc.y, pp.y);
        pp.z = fmaf(-vv[k], wc.z, pp.z); pp.w = fmaf(-vv[k], wc.w, pp.w);
    }
    *(float4*)&g_q[p*HID + c] = q;
    *(float4*)&g_p[p*HID + c] = pp;

    float sq  = (q.x + q.y) + (q.z + q.w);
    float sq2 = fmaf(q.x,q.x, fmaf(q.y,q.y, fmaf(q.z,q.z, q.w*q.w)));
    float sp  = (pp.x + pp.y) + (pp.z + pp.w);
    float sp2 = fmaf(pp.x,pp.x, fmaf(pp.y,pp.y, fmaf(pp.z,pp.z, pp.w*pp.w)));
#pragma unroll
    for (int off = 16; off; off >>= 1) {
        sq  += __shfl_xor_sync(FULLM, sq,  off);
        sq2 += __shfl_xor_sync(FULLM, sq2, off);
        sp  += __shfl_xor_sync(FULLM, sp,  off);
        sp2 += __shfl_xor_sync(FULLM, sp2, off);
    }
    if (lane == 0) g_stat[p] = make_float4(sq, sq2, sp, sp2);
}

// ---------------------------------------------------------------------------
__device__ __forceinline__ float gelu_fast(float x) {
    float z2 = 1.5957691216057308f * fmaf(0.044715f * x * x, x, x);
    float e  = __expf(z2);
    float r  = __fdividef(1.0f, e + 1.0f);
    return x - x * r;
}

// ---------------------------------------------------------------------------
// Edge kernel: warp per point, four interleaved reduction chains.
// ---------------------------------------------------------------------------
__global__ void __launch_bounds__(256) edge_kernel(
    const float* __restrict__ g1, const float* __restrict__ be1,
    const float* __restrict__ W2, const float* __restrict__ b2)
{
    __shared__ float sW2[HID*COUT];   // 32KB
    int tid = threadIdx.x, lane = tid & 31, w = tid >> 5;
    for (int e = tid; e < HID*COUT; e += 256) sW2[e] = W2[e];
    __syncthreads();

    int p = blockIdx.x * 8 + w;
    int myidx = (lane < KNN) ? g_idx[p*KNN + lane] : 0;
    int c = lane * 4;

    float4 P4  = *(const float4*)&g_p[p*HID + c];
    float4 g1v = *(const float4*)&g1[c];
    float4 bev = *(const float4*)&be1[c];
    float4 stP = g_stat[p];
    float4 stN = __ldg(&g_stat[myidx]);
    float sumn = stN.x + stP.z;
    float bsqn = stN.y + stP.w;

    float4 accG = make_float4(0.f,0.f,0.f,0.f);

    float4 qn[4];
#pragma unroll
    for (int r = 0; r < 4; r++) {
        int nb = __shfl_sync(FULLM, myidx, r);
        qn[r] = __ldg((const float4*)&g_q[nb*HID + c]);
    }

#pragma unroll
    for (int n = 0; n < KNN; n += 4) {
        float4 h[4];
        float dp[4];
#pragma unroll
        for (int r = 0; r < 4; r++) {
            h[r].x = qn[r].x + P4.x; h[r].y = qn[r].y + P4.y;
            h[r].z = qn[r].z + P4.z; h[r].w = qn[r].w + P4.w;
            dp[r] = fmaf(qn[r].x,P4.x, fmaf(qn[r].y,P4.y, fmaf(qn[r].z,P4.z, qn[r].w*P4.w)));
        }
        if (n + 4 < KNN) {
#pragma unroll
            for (int r = 0; r < 4; r++) {
                int nb = __shfl_sync(FULLM, myidx, n + 4 + r);
                qn[r] = __ldg((const float4*)&g_q[nb*HID + c]);
            }
        }
#pragma unroll
        for (int off = 16; off; off >>= 1) {
#pragma unroll
            for (int r = 0; r < 4; r++)
                dp[r] += __shfl_xor_sync(FULLM, dp[r], off);
        }
#pragma unroll
        for (int r = 0; r < 4; r++) {
            float sum = __shfl_sync(FULLM, sumn, n + r);
            float bsq = __shfl_sync(FULLM, bsqn, n + r);
            float mu  = sum * (1.f/HID);
            float e2  = fmaf(2.0f, dp[r], bsq) * (1.f/HID);
            float rs  = rsqrtf(e2 - mu*mu + 1e-5f);
            accG.x += gelu_fast(fmaf((h[r].x - mu)*rs, g1v.x, bev.x));
            accG.y += gelu_fast(fmaf((h[r].y - mu)*rs, g1v.y, bev.y));
            accG.z += gelu_fast(fmaf((h[r].z - mu)*rs, g1v.z, bev.z));
            accG.w += gelu_fast(fmaf((h[r].w - mu)*rs, g1v.w, bev.w));
        }
    }
    accG.x *= (1.f/KNN); accG.y *= (1.f/KNN);
    accG.z *= (1.f/KNN); accG.w *= (1.f/KNN);

    float m0 = __ldg(&b2[lane]);
    float m1 = __ldg(&b2[lane + 32]);
#pragma unroll
    for (int src = 0; src < 32; src++) {
        float gx = __shfl_sync(FULLM, accG.x, src);
        float gy = __shfl_sync(FULLM, accG.y, src);
        float gz = __shfl_sync(FULLM, accG.z, src);
        float gw = __shfl_sync(FULLM, accG.w, src);
        int k0 = src * 4;
        m0 = fmaf(gx, sW2[(k0+0)*COUT + lane], m0);
        m0 = fmaf(gy, sW2[(k0+1)*COUT + lane], m0);
        m0 = fmaf(gz, sW2[(k0+2)*COUT + lane], m0);
        m0 = fmaf(gw, sW2[(k0+3)*COUT + lane], m0);
        m1 = fmaf(gx, sW2[(k0+0)*COUT + lane + 32], m1);
        m1 = fmaf(gy, sW2[(k0+1)*COUT + lane + 32], m1);
        m1 = fmaf(gz, sW2[(k0+2)*COUT + lane + 32], m1);
        m1 = fmaf(gw, sW2[(k0+3)*COUT + lane + 32], m1);
    }
    g_mid[p*COUT + lane]      = m0;
    g_mid[p*COUT + lane + 32] = m1;
}

// ---------------------------------------------------------------------------
// MLP2 fused: 64 points per block, grid 256.
// ---------------------------------------------------------------------------
#define M2PTS 64
#define SMEM2_FLOATS (COUT*M2PTS + COUT*HID + HID*COUT)  // 20480

__global__ void __launch_bounds__(256, 2) mlp2_kernel(
    const float* __restrict__ Wo1, const float* __restrict__ bo1,
    const float* __restrict__ go,  const float* __restrict__ beo,
    const float* __restrict__ Wo2, const float* __restrict__ bo2,
    float* __restrict__ out)
{
    extern __shared__ float sm[];
    float* sAt  = sm;
    float* sWo1 = sm + COUT*M2PTS;
    float* sH   = sm;                          // aliases sAt+sWo1
    float* sWo2 = sm + COUT*M2PTS + COUT*HID;

    int tid = threadIdx.x;
    int r0  = blockIdx.x * M2PTS;

    for (int e = tid; e < COUT*HID; e += 256) sWo1[e] = Wo1[e];
    for (int e = tid; e < HID*COUT; e += 256) sWo2[e] = Wo2[e];
    for (int e = tid; e < COUT*M2PTS; e += 256) {
        int r = e & (M2PTS-1), k = e >> 6;
        sAt[k*M2PTS + r] = g_mid[(r0 + r)*COUT + k];
    }
    __syncthreads();

    int tx = tid & 15, ty = tid >> 4;

    float acc[4][8];
#pragma unroll
    for (int i = 0; i < 4; i++)
#pragma unroll
        for (int j = 0; j < 8; j++) acc[i][j] = 0.f;

    for (int k = 0; k < COUT; k++) {
        float4 a4 = *(const float4*)&sAt[k*M2PTS + ty*4];
        float4 c0 = *(const float4*)&sWo1[k*HID + tx*8];
        float4 c1 = *(const float4*)&sWo1[k*HID + tx*8 + 4];
        float a[4] = {a4.x,a4.y,a4.z,a4.w};
        float wv[8] = {c0.x,c0.y,c0.z,c0.w,c1.x,c1.y,c1.z,c1.w};
#pragma unroll
        for (int i = 0; i < 4; i++)
#pragma unroll
            for (int j = 0; j < 8; j++)
                acc[i][j] = fmaf(a[i], wv[j], acc[i][j]);
    }

    __syncthreads();

    float b1j[8], gj[8], bej[8];
#pragma unroll
    for (int j = 0; j < 8; j++) {
        int col = tx*8 + j;
        b1j[j] = bo1[col]; gj[j] = go[col]; bej[j] = beo[col];
    }
#pragma unroll
    for (int i = 0; i < 4; i++) {
        float ps = 0.f, ps2 = 0.f;
#pragma unroll
        for (int j = 0; j < 8; j++) {
            float h = acc[i][j] + b1j[j];
            acc[i][j] = h;
            ps += h; ps2 = fmaf(h, h, ps2);
        }
#pragma unroll
        for (int off = 8; off; off >>= 1) {
            ps  += __shfl_xor_sync(FULLM, ps,  off);
            ps2 += __shfl_xor_sync(FULLM, ps2, off);
        }
        float mu  = ps  * (1.f/HID);
        float var = ps2 * (1.f/HID) - mu*mu;
        float rs  = rsqrtf(var + 1e-5f);
        float o[8];
#pragma unroll
        for (int j = 0; j < 8; j++)
            o[j] = gelu_fast(fmaf((acc[i][j] - mu)*rs, gj[j], bej[j]));
        int row = ty*4 + i;
        *(float4*)&sH[row*132 + tx*8]     = make_float4(o[0],o[1],o[2],o[3]);
        *(float4*)&sH[row*132 + tx*8 + 4] = make_float4(o[4],o[5],o[6],o[7]);
    }
    __syncthreads();

    float acc2[4][4];
#pragma unroll
    for (int i = 0; i < 4; i++)
#pragma unroll
        for (int j = 0; j < 4; j++) acc2[i][j] = 0.f;

    for (int k = 0; k < HID; k += 4) {
        float4 w0 = *(const float4*)&sWo2[(k+0)*COUT + tx*4];
        float4 w1 = *(const float4*)&sWo2[(k+1)*COUT + tx*4];
        float4 w2 = *(const float4*)&sWo2[(k+2)*COUT + tx*4];
        float4 w3 = *(const float4*)&sWo2[(k+3)*COUT + tx*4];
#pragma unroll
        for (int i = 0; i < 4; i++) {
            float4 av = *(const float4*)&sH[(ty*4+i)*132 + k];
            acc2[i][0] = fmaf(av.x, w0.x, fmaf(av.y, w1.x, fmaf(av.z, w2.x, fmaf(av.w, w3.x, acc2[i][0]))));
            acc2[i][1] = fmaf(av.x, w0.y, fmaf(av.y, w1.y, fmaf(av.z, w2.y, fmaf(av.w, w3.y, acc2[i][1]))));
            acc2[i][2] = fmaf(av.x, w0.z, fmaf(av.y, w1.z, fmaf(av.z, w2.z, fmaf(av.w, w3.z, acc2[i][2]))));
            acc2[i][3] = fmaf(av.x, w0.w, fmaf(av.y, w1.w, fmaf(av.z, w2.w, fmaf(av.w, w3.w, acc2[i][3]))));
        }
    }

    float b2j[4];
#pragma unroll
    for (int j = 0; j < 4; j++) b2j[j] = bo2[tx*4 + j];
#pragma unroll
    for (int i = 0; i < 4; i++) {
        int row = r0 + ty*4 + i;
#pragma unroll
        for (int j = 0; j < 4; j++)
            out[row*COUT + tx*4 + j] = acc2[i][j] + b2j[j];
    }
}

// ---------------------------------------------------------------------------
extern "C" void kernel_launch(void* const* d_in, const int* in_sizes, int n_in,
                              void* d_out, int out_size) {
    const float* verts = (const float*)d_in[0];
    const float* feat  = (const float*)d_in[1];
    const float* W1    = (const float*)d_in[2];
    const float* b1    = (const float*)d_in[3];
    const float* g1    = (const float*)d_in[4];
    const float* be1   = (const float*)d_in[5];
    const float* W2    = (const float*)d_in[6];
    const float* b2    = (const float*)d_in[7];
    const float* Wo1   = (const float*)d_in[8];
    const float* bo1   = (const float*)d_in[9];
    const float* go    = (const float*)d_in[10];
    const float* beo   = (const float*)d_in[11];
    const float* Wo2   = (const float*)d_in[12];
    const float* bo2   = (const float*)d_in[13];
    float* out = (float*)d_out;

    const int smem2 = SMEM2_FLOATS * 4;   // 81920
    cudaFuncSetAttribute(mlp2_kernel, cudaFuncAttributeMaxDynamicSharedMemorySize, smem2);

    prep_kernel<<<(TOT + 255)/256, 256>>>(verts);
    bin_kernel<<<(TOT + 255)/256, 256>>>();
    scan_kernel<<<BN, 1024>>>();
    scatter_kernel<<<(TOT + 255)/256, 256>>>();
    knn_kernel<<<TOT/8, 256>>>();
    precomp_kernel<<<TOT/8, 256>>>(verts, feat, W1, b1);
    edge_kernel<<<TOT/8, 256>>>(g1, be1, W2, b2);
    mlp2_kernel<<<TOT/M2PTS, 256, smem2>>>(Wo1, bo1, go, beo, Wo2, bo2, out);
}

// round 16
// speedup vs baseline: 1.4813x; 1.1003x over previous
#include <cuda_runtime.h>
#include <math.h>

#define BN   2
#define NPTS 8192
#define KNN  16
#define CIN  32
#define EIN  67      // 32 + 32 + 3
#define HID  128
#define COUT 64
#define TOT  (BN*NPTS)
#define FULLM 0xffffffffu
#define FMAX  3.402823466e38f

// 3-D cell sort for KNN: 16^3 cells, z contiguous (lex order bx,by,bz)
#define NC3    16
#define CELLS3 (NC3*NC3*NC3)     // 4096 per batch
#define XMIN  (-4.65f)
#define XSPAN 9.3f
#define BW3   (XSPAN/NC3)        // 0.58125
#define INVBW3 (NC3/XSPAN)

// Scratch (no allocations allowed)
__device__ int    g_idx[TOT*KNN];
__device__ float  g_mid[TOT*COUT];
__device__ float4 g_vert4[TOT];
__device__ float  g_q[TOT*HID];
__device__ float  g_p[TOT*HID];
__device__ float4 g_stat[TOT];
__device__ int    g_ccnt[BN][CELLS3];
__device__ int    g_cstart[BN][CELLS3+1];
__device__ int    g_ccur[BN][CELLS3];
__device__ float4 g_sx4[TOT];              // cell-sorted points
__device__ int    g_ssid[TOT];             // sorted -> original GLOBAL index

// ---------------------------------------------------------------------------
__global__ void prep_kernel(const float* __restrict__ verts) {
    int i = blockIdx.x * blockDim.x + threadIdx.x;
    if (i < TOT) {
        float x = verts[i*3+0], y = verts[i*3+1], z = verts[i*3+2];
        g_vert4[i] = make_float4(x, y, z, x*x + y*y + z*z);
    }
    if (i < BN*CELLS3) ((int*)g_ccnt)[i] = 0;
}

__device__ __forceinline__ int clampi(int v, int lo, int hi) {
    return v < lo ? lo : (v > hi ? hi : v);
}

__global__ void bin_kernel() {
    int i = blockIdx.x * blockDim.x + threadIdx.x;
    if (i >= TOT) return;
    float4 v = g_vert4[i];
    int bx = clampi((int)((v.x - XMIN) * INVBW3), 0, NC3-1);
    int by = clampi((int)((v.y - XMIN) * INVBW3), 0, NC3-1);
    int bz = clampi((int)((v.z - XMIN) * INVBW3), 0, NC3-1);
    atomicAdd(&g_ccnt[i >> 13][(bx*NC3 + by)*NC3 + bz], 1);
}

// One block per batch, 1024 threads, 4 cells/thread + block-wide scan.
__global__ void scan_kernel() {
    __shared__ int s[1024];
    int bb = blockIdx.x, t = threadIdx.x;
    int lo = t*4;
    int loc[4]; int sum = 0;
#pragma unroll
    for (int k = 0; k < 4; k++) { loc[k] = g_ccnt[bb][lo+k]; sum += loc[k]; }
    s[t] = sum;
    __syncthreads();
    for (int d = 1; d < 1024; d <<= 1) {
        int u = (t >= d) ? s[t-d] : 0;
        __syncthreads();
        s[t] += u;
        __syncthreads();
    }
    int run = s[t] - sum;
#pragma unroll
    for (int k = 0; k < 4; k++) {
        g_cstart[bb][lo+k] = run;
        g_ccur[bb][lo+k]   = run;
        run += loc[k];
    }
    if (t == 1023) g_cstart[bb][CELLS3] = NPTS;
}

__global__ void scatter_kernel() {
    int i = blockIdx.x * blockDim.x + threadIdx.x;
    if (i >= TOT) return;
    float4 v = g_vert4[i];
    int bb = i >> 13;
    int bx = clampi((int)((v.x - XMIN) * INVBW3), 0, NC3-1);
    int by = clampi((int)((v.y - XMIN) * INVBW3), 0, NC3-1);
    int bz = clampi((int)((v.z - XMIN) * INVBW3), 0, NC3-1);
    int slot = bb * NPTS + atomicAdd(&g_ccur[bb][(bx*NC3 + by)*NC3 + bz], 1);
    g_sx4[slot]  = v;
    g_ssid[slot] = i;
}

// ---------------------------------------------------------------------------
// Scan sorted segment [a,b) through the warp's ascending lane-sorted best-32
// queue (batch-frozen threshold; identical distance formula as brute force).
// ---------------------------------------------------------------------------
__device__ __forceinline__ void scan_seg(int a, int b, int sbase, float4 qv,
                                         int lane, float& key, int& idx) {
    for (int i = a; i < b; i += 32) {
        int j = i + lane;
        float d = FMAX;
        if (j < b) {
            float4 c = __ldg(&g_sx4[sbase + j]);
            float dot = fmaf(qv.x, c.x, fmaf(qv.y, c.y, qv.z*c.z));
            d = fmaf(-2.0f, dot, qv.w + c.w);
        }
        float thb = __shfl_sync(FULLM, key, 15);
        unsigned mask = __ballot_sync(FULLM, d < thb);
        while (mask) {
            int src = __ffs(mask) - 1;
            mask &= mask - 1;
            float v  = __shfl_sync(FULLM, d, src);
            int   vi = i + src;
            float pk = __shfl_up_sync(FULLM, key, 1);
            int   pi = __shfl_up_sync(FULLM, idx, 1);
            if (v < key) {
                if (lane > 0 && v < pk) { key = pk; idx = pi; }
                else                    { key = v;  idx = vi; }
            }
        }
    }
}

// ---------------------------------------------------------------------------
// KNN: warp per query over 3-D sorted cells, CSR in SMEM. Start from the
// CENTER CELL ONLY (~100 pts at core density; r16 ~0.2 << cell 0.58), then
// face-wise expansion on the min of six gaps until the exact covering bound.
// ---------------------------------------------------------------------------
__global__ void __launch_bounds__(256) knn_kernel() {
    __shared__ int scs[CELLS3+1];    // 16.4KB
    int tid  = threadIdx.x;
    int lane = tid & 31;
    int w    = tid >> 5;
    int gq   = blockIdx.x * 8 + w;
    int bb   = gq >> 13;
    int sbase = bb * NPTS;

    for (int i = tid; i <= CELLS3; i += 256) scs[i] = g_cstart[bb][i];
    __syncthreads();

    float4 qv = g_vert4[gq];
    int bx0 = clampi((int)((qv.x - XMIN) * INVBW3), 0, NC3-1);
    int by0 = clampi((int)((qv.y - XMIN) * INVBW3), 0, NC3-1);
    int bz0 = clampi((int)((qv.z - XMIN) * INVBW3), 0, NC3-1);

    int xlo = bx0, xhi = bx0;
    int ylo = by0, yhi = by0;
    int zlo = bz0, zhi = bz0;

    // --- bitonic warm-start: first 32 of the center cell ---
    int cb0 = (bx0*NC3 + by0)*NC3;
    int a0 = scs[cb0 + bz0], b0 = scs[cb0 + bz0 + 1];
    float key; int idx;
    {
        float d = FMAX; int vi = 0;
        int j = a0 + lane;
        if (j < b0) {
            float4 c = __ldg(&g_sx4[sbase + j]);
            float dot = fmaf(qv.x, c.x, fmaf(qv.y, c.y, qv.z*c.z));
            d = fmaf(-2.0f, dot, qv.w + c.w);
            vi = j;
        }
#pragma unroll
        for (int k = 2; k <= 32; k <<= 1) {
#pragma unroll
            for (int s = k >> 1; s > 0; s >>= 1) {
                int partner = lane ^ s;
                float ok = __shfl_xor_sync(FULLM, d,  s);
                int   oi = __shfl_xor_sync(FULLM, vi, s);
                bool dir = ((lane & k) == 0);
                bool otherLess = (ok < d) || (ok == d && partner < lane);
                bool lower = ((lane & s) == 0);
                bool take = (lower == dir) ? otherLess : !otherLess;
                if (take) { d = ok; vi = oi; }
            }
        }
        key = d; idx = vi;
    }
    scan_seg(min(a0 + 32, b0), b0, sbase, qv, lane, key, idx);

    for (;;) {
        float gxl = (xlo == 0)       ? FMAX : qv.x - (XMIN + xlo * BW3);
        float gxh = (xhi == NC3 - 1) ? FMAX : (XMIN + (xhi + 1) * BW3) - qv.x;
        float gyl = (ylo == 0)       ? FMAX : qv.y - (XMIN + ylo * BW3);
        float gyh = (yhi == NC3 - 1) ? FMAX : (XMIN + (yhi + 1) * BW3) - qv.y;
        float gzl = (zlo == 0)       ? FMAX : qv.z - (XMIN + zlo * BW3);
        float gzh = (zhi == NC3 - 1) ? FMAX : (XMIN + (zhi + 1) * BW3) - qv.z;
        float bnd = fminf(fminf(fminf(gxl, gxh), fminf(gyl, gyh)), fminf(gzl, gzh));
        if (bnd > 1e37f) break;                       // everything scanned
        float th = __shfl_sync(FULLM, key, 15);
        if (th <= bnd * bnd) break;                   // exact 3-D stop bound

        if (gxl <= gxh && gxl <= gyl && gxl <= gyh && gxl <= gzl && gxl <= gzh) {
            xlo--;
            for (int by = ylo; by <= yhi; by++) {
                int cb = (xlo*NC3 + by)*NC3;
                scan_seg(scs[cb + zlo], scs[cb + zhi + 1], sbase, qv, lane, key, idx);
            }
        } else if (gxh <= gyl && gxh <= gyh && gxh <= gzl && gxh <= gzh) {
            xhi++;
            for (int by = ylo; by <= yhi; by++) {
                int cb = (xhi*NC3 + by)*NC3;
                scan_seg(scs[cb + zlo], scs[cb + zhi + 1], sbase, qv, lane, key, idx);
            }
        } else if (gyl <= gyh && gyl <= gzl && gyl <= gzh) {
            ylo--;
            for (int bx = xlo; bx <= xhi; bx++) {
                int cb = (bx*NC3 + ylo)*NC3;
                scan_seg(scs[cb + zlo], scs[cb + zhi + 1], sbase, qv, lane, key, idx);
            }
        } else if (gyh <= gzl && gyh <= gzh) {
            yhi++;
            for (int bx = xlo; bx <= xhi; bx++) {
                int cb = (bx*NC3 + yhi)*NC3;
                scan_seg(scs[cb + zlo], scs[cb + zhi + 1], sbase, qv, lane, key, idx);
            }
        } else if (gzl <= gzh) {
            zlo--;
            for (int bx = xlo; bx <= xhi; bx++)
                for (int by = ylo; by <= yhi; by++) {
                    int cb = (bx*NC3 + by)*NC3;
                    scan_seg(scs[cb + zlo], scs[cb + zlo + 1], sbase, qv, lane, key, idx);
                }
        } else {
            zhi++;
            for (int bx = xlo; bx <= xhi; bx++)
                for (int by = ylo; by <= yhi; by++) {
                    int cb = (bx*NC3 + by)*NC3;
                    scan_seg(scs[cb + zhi], scs[cb + zhi + 1], sbase, qv, lane, key, idx);
                }
        }
    }

    if (lane < KNN) g_idx[gq*KNN + lane] = g_ssid[sbase + idx];
}

// ---------------------------------------------------------------------------
// Precompute Q[n], P[n] and their channel sums / sum-of-squares.
// ---------------------------------------------------------------------------
__global__ void __launch_bounds__(256) precomp_kernel(
    const float* __restrict__ verts, const float* __restrict__ feat,
    const float* __restrict__ W1, const float* __restrict__ b1)
{
    __shared__ float sW1[EIN*HID];   // 34.3KB
    int tid = threadIdx.x, lane = tid & 31, w = tid >> 5;
    for (int e = tid; e < EIN*HID; e += 256) sW1[e] = W1[e];
    __syncthreads();

    int p = blockIdx.x * 8 + w;
    float4 f4 = make_float4(0.f,0.f,0.f,0.f);
    if (lane < 8) f4 = *(const float4*)&feat[p*CIN + lane*4];
    float vx = verts[p*3+0], vy = verts[p*3+1], vz = verts[p*3+2];

    int c = lane*4;
    float4 q  = make_float4(0.f,0.f,0.f,0.f);
    float4 pp = *(const float4*)&b1[c];

#pragma unroll
    for (int src = 0; src < 8; src++) {
        float fx = __shfl_sync(FULLM, f4.x, src);
        float fy = __shfl_sync(FULLM, f4.y, src);
        float fz = __shfl_sync(FULLM, f4.z, src);
        float fw = __shfl_sync(FULLM, f4.w, src);
        float fv[4] = {fx, fy, fz, fw};
        int k0 = src*4;
#pragma unroll
        for (int kk = 0; kk < 4; kk++) {
            int k = k0 + kk;
            float4 wa = *(const float4*)&sW1[k*HID + c];
            float4 wb = *(const float4*)&sW1[(CIN + k)*HID + c];
            q.x  = fmaf(fv[kk], wa.x, q.x);  q.y  = fmaf(fv[kk], wa.y, q.y);
            q.z  = fmaf(fv[kk], wa.z, q.z);  q.w  = fmaf(fv[kk], wa.w, q.w);
            pp.x = fmaf(fv[kk], wb.x, pp.x); pp.y = fmaf(fv[kk], wb.y, pp.y);
            pp.z = fmaf(fv[kk], wb.z, pp.z); pp.w = fmaf(fv[kk], wb.w, pp.w);
        }
    }
    float vv[3] = {vx, vy, vz};
#pragma unroll
    for (int k = 0; k < 3; k++) {
        float4 wc = *(const float4*)&sW1[(2*CIN + k)*HID + c];
        q.x  = fmaf(vv[k],  wc.x, q.x);  q.y  = fmaf(vv[k],  wc.y, q.y);
        q.z  = fmaf(vv[k],  wc.z, q.z);  q.w  = fmaf(vv[k],  wc.w, q.w);
        pp.x = fmaf(-vv[k], wc.x, pp.x); pp.y = fmaf(-vv[k], wc.y, pp.y);
        pp.z = fmaf(-vv[k], wc.z, pp.z); pp.w = fmaf(-vv[k], wc.w, pp.w);
    }
    *(float4*)&g_q[p*HID + c] = q;
    *(float4*)&g_p[p*HID + c] = pp;

    float sq  = (q.x + q.y) + (q.z + q.w);
    float sq2 = fmaf(q.x,q.x, fmaf(q.y,q.y, fmaf(q.z,q.z, q.w*q.w)));
    float sp  = (pp.x + pp.y) + (pp.z + pp.w);
    float sp2 = fmaf(pp.x,pp.x, fmaf(pp.y,pp.y, fmaf(pp.z,pp.z, pp.w*pp.w)));
#pragma unroll
    for (int off = 16; off; off >>= 1) {
        sq  += __shfl_xor_sync(FULLM, sq,  off);
        sq2 += __shfl_xor_sync(FULLM, sq2, off);
        sp  += __shfl_xor_sync(FULLM, sp,  off);
        sp2 += __shfl_xor_sync(FULLM, sp2, off);
    }
    if (lane == 0) g_stat[p] = make_float4(sq, sq2, sp, sp2);
}

// ---------------------------------------------------------------------------
__device__ __forceinline__ float gelu_fast(float x) {
    float z2 = 1.5957691216057308f * fmaf(0.044715f * x * x, x, x);
    float e  = __expf(z2);
    float r  = __fdividef(1.0f, e + 1.0f);
    return x - x * r;
}

// ---------------------------------------------------------------------------
// Edge kernel: warp per point, four interleaved reduction chains. Final GEMM
// via per-warp SMEM stage of accG (broadcast LDS.128 instead of shfl) and
// float2 W2 column pairs (lane -> cols 2l, 2l+1).
// ---------------------------------------------------------------------------
__global__ void __launch_bounds__(256) edge_kernel(
    const float* __restrict__ g1, const float* __restrict__ be1,
    const float* __restrict__ W2, const float* __restrict__ b2)
{
    __shared__ float sW2[HID*COUT];   // 32KB
    __shared__ float sGa[8][HID];     // 4KB, per-warp accG stage
    int tid = threadIdx.x, lane = tid & 31, w = tid >> 5;
    for (int e = tid; e < HID*COUT; e += 256) sW2[e] = W2[e];
    __syncthreads();

    int p = blockIdx.x * 8 + w;
    int myidx = (lane < KNN) ? g_idx[p*KNN + lane] : 0;
    int c = lane * 4;

    float4 P4  = *(const float4*)&g_p[p*HID + c];
    float4 g1v = *(const float4*)&g1[c];
    float4 bev = *(const float4*)&be1[c];
    float4 stP = g_stat[p];
    float4 stN = __ldg(&g_stat[myidx]);
    float sumn = stN.x + stP.z;
    float bsqn = stN.y + stP.w;

    float4 accG = make_float4(0.f,0.f,0.f,0.f);

    float4 qn[4];
#pragma unroll
    for (int r = 0; r < 4; r++) {
        int nb = __shfl_sync(FULLM, myidx, r);
        qn[r] = __ldg((const float4*)&g_q[nb*HID + c]);
    }

#pragma unroll
    for (int n = 0; n < KNN; n += 4) {
        float4 h[4];
        float dp[4];
#pragma unroll
        for (int r = 0; r < 4; r++) {
            h[r].x = qn[r].x + P4.x; h[r].y = qn[r].y + P4.y;
            h[r].z = qn[r].z + P4.z; h[r].w = qn[r].w + P4.w;
            dp[r] = fmaf(qn[r].x,P4.x, fmaf(qn[r].y,P4.y, fmaf(qn[r].z,P4.z, qn[r].w*P4.w)));
        }
        if (n + 4 < KNN) {
#pragma unroll
            for (int r = 0; r < 4; r++) {
                int nb = __shfl_sync(FULLM, myidx, n + 4 + r);
                qn[r] = __ldg((const float4*)&g_q[nb*HID + c]);
            }
        }
#pragma unroll
        for (int off = 16; off; off >>= 1) {
#pragma unroll
            for (int r = 0; r < 4; r++)
                dp[r] += __shfl_xor_sync(FULLM, dp[r], off);
        }
#pragma unroll
        for (int r = 0; r < 4; r++) {
            float sum = __shfl_sync(FULLM, sumn, n + r);
            float bsq = __shfl_sync(FULLM, bsqn, n + r);
            float mu  = sum * (1.f/HID);
            float e2  = fmaf(2.0f, dp[r], bsq) * (1.f/HID);
            float rs  = rsqrtf(e2 - mu*mu + 1e-5f);
            accG.x += gelu_fast(fmaf((h[r].x - mu)*rs, g1v.x, bev.x));
            accG.y += gelu_fast(fmaf((h[r].y - mu)*rs, g1v.y, bev.y));
            accG.z += gelu_fast(fmaf((h[r].z - mu)*rs, g1v.z, bev.z));
            accG.w += gelu_fast(fmaf((h[r].w - mu)*rs, g1v.w, bev.w));
        }
    }
    accG.x *= (1.f/KNN); accG.y *= (1.f/KNN);
    accG.z *= (1.f/KNN); accG.w *= (1.f/KNN);

    // stage accG in smem; lane handles output cols 2*lane, 2*lane+1
    *(float4*)&sGa[w][c] = accG;
    __syncwarp();

    float2 b2v = *(const float2*)&b2[2*lane];
    float m0 = b2v.x, m1 = b2v.y;
    const float* gw = sGa[w];
#pragma unroll 4
    for (int k0 = 0; k0 < HID; k0 += 4) {
        float4 g4 = *(const float4*)&gw[k0];
        float2 w0 = *(const float2*)&sW2[(k0+0)*COUT + 2*lane];
        float2 w1 = *(const float2*)&sW2[(k0+1)*COUT + 2*lane];
        float2 w2 = *(const float2*)&sW2[(k0+2)*COUT + 2*lane];
        float2 w3 = *(const float2*)&sW2[(k0+3)*COUT + 2*lane];
        m0 = fmaf(g4.x, w0.x, m0); m1 = fmaf(g4.x, w0.y, m1);
        m0 = fmaf(g4.y, w1.x, m0); m1 = fmaf(g4.y, w1.y, m1);
        m0 = fmaf(g4.z, w2.x, m0); m1 = fmaf(g4.z, w2.y, m1);
        m0 = fmaf(g4.w, w3.x, m0); m1 = fmaf(g4.w, w3.y, m1);
    }
    *(float2*)&g_mid[p*COUT + 2*lane] = make_float2(m0, m1);
}

// ---------------------------------------------------------------------------
// MLP2 fused: 64 points per block, grid 256.
// ---------------------------------------------------------------------------
#define M2PTS 64
#define SMEM2_FLOATS (COUT*M2PTS + COUT*HID + HID*COUT)  // 20480

__global__ void __launch_bounds__(256, 2) mlp2_kernel(
    const float* __restrict__ Wo1, const float* __restrict__ bo1,
    const float* __restrict__ go,  const float* __restrict__ beo,
    const float* __restrict__ Wo2, const float* __restrict__ bo2,
    float* __restrict__ out)
{
    extern __shared__ float sm[];
    float* sAt  = sm;
    float* sWo1 = sm + COUT*M2PTS;
    float* sH   = sm;                          // aliases sAt+sWo1
    float* sWo2 = sm + COUT*M2PTS + COUT*HID;

    int tid = threadIdx.x;
    int r0  = blockIdx.x * M2PTS;

    for (int e = tid; e < COUT*HID; e += 256) sWo1[e] = Wo1[e];
    for (int e = tid; e < HID*COUT; e += 256) sWo2[e] = Wo2[e];
    for (int e = tid; e < COUT*M2PTS; e += 256) {
        int r = e & (M2PTS-1), k = e >> 6;
        sAt[k*M2PTS + r] = g_mid[(r0 + r)*COUT + k];
    }
    __syncthreads();

    int tx = tid & 15, ty = tid >> 4;

    float acc[4][8];
#pragma unroll
    for (int i = 0; i < 4; i++)
#pragma unroll
        for (int j = 0; j < 8; j++) acc[i][j] = 0.f;

    for (int k = 0; k < COUT; k++) {
        float4 a4 = *(const float4*)&sAt[k*M2PTS + ty*4];
        float4 c0 = *(const float4*)&sWo1[k*HID + tx*8];
        float4 c1 = *(const float4*)&sWo1[k*HID + tx*8 + 4];
        float a[4] = {a4.x,a4.y,a4.z,a4.w};
        float wv[8] = {c0.x,c0.y,c0.z,c0.w,c1.x,c1.y,c1.z,c1.w};
#pragma unroll
        for (int i = 0; i < 4; i++)
#pragma unroll
            for (int j = 0; j < 8; j++)
                acc[i][j] = fmaf(a[i], wv[j], acc[i][j]);
    }

    __syncthreads();

    float b1j[8], gj[8], bej[8];
#pragma unroll
    for (int j = 0; j < 8; j++) {
        int col = tx*8 + j;
        b1j[j] = bo1[col]; gj[j] = go[col]; bej[j] = beo[col];
    }
#pragma unroll
    for (int i = 0; i < 4; i++) {
        float ps = 0.f, ps2 = 0.f;
#pragma unroll
        for (int j = 0; j < 8; j++) {
            float h = acc[i][j] + b1j[j];
            acc[i][j] = h;
            ps += h; ps2 = fmaf(h, h, ps2);
        }
#pragma unroll
        for (int off = 8; off; off >>= 1) {
            ps  += __shfl_xor_sync(FULLM, ps,  off);
            ps2 += __shfl_xor_sync(FULLM, ps2, off);
        }
        float mu  = ps  * (1.f/HID);
        float var = ps2 * (1.f/HID) - mu*mu;
        float rs  = rsqrtf(var + 1e-5f);
        float o[8];
#pragma unroll
        for (int j = 0; j < 8; j++)
            o[j] = gelu_fast(fmaf((acc[i][j] - mu)*rs, gj[j], bej[j]));
        int row = ty*4 + i;
        *(float4*)&sH[row*132 + tx*8]     = make_float4(o[0],o[1],o[2],o[3]);
        *(float4*)&sH[row*132 + tx*8 + 4] = make_float4(o[4],o[5],o[6],o[7]);
    }
    __syncthreads();

    float acc2[4][4];
#pragma unroll
    for (int i = 0; i < 4; i++)
#pragma unroll
        for (int j = 0; j < 4; j++) acc2[i][j] = 0.f;

    for (int k = 0; k < HID; k += 4) {
        float4 w0 = *(const float4*)&sWo2[(k+0)*COUT + tx*4];
        float4 w1 = *(const float4*)&sWo2[(k+1)*COUT + tx*4];
        float4 w2 = *(const float4*)&sWo2[(k+2)*COUT + tx*4];
        float4 w3 = *(const float4*)&sWo2[(k+3)*COUT + tx*4];
#pragma unroll
        for (int i = 0; i < 4; i++) {
            float4 av = *(const float4*)&sH[(ty*4+i)*132 + k];
            acc2[i][0] = fmaf(av.x, w0.x, fmaf(av.y, w1.x, fmaf(av.z, w2.x, fmaf(av.w, w3.x, acc2[i][0]))));
            acc2[i][1] = fmaf(av.x, w0.y, fmaf(av.y, w1.y, fmaf(av.z, w2.y, fmaf(av.w, w3.y, acc2[i][1]))));
            acc2[i][2] = fmaf(av.x, w0.z, fmaf(av.y, w1.z, fmaf(av.z, w2.z, fmaf(av.w, w3.z, acc2[i][2]))));
            acc2[i][3] = fmaf(av.x, w0.w, fmaf(av.y, w1.w, fmaf(av.z, w2.w, fmaf(av.w, w3.w, acc2[i][3]))));
        }
    }

    float b2j[4];
#pragma unroll
    for (int j = 0; j < 4; j++) b2j[j] = bo2[tx*4 + j];
#pragma unroll
    for (int i = 0; i < 4; i++) {
        int row = r0 + ty*4 + i;
#pragma unroll
        for (int j = 0; j < 4; j++)
            out[row*COUT + tx*4 + j] = acc2[i][j] + b2j[j];
    }
}

// ---------------------------------------------------------------------------
extern "C" void kernel_launch(void* const* d_in, const int* in_sizes, int n_in,
                              void* d_out, int out_size) {
    const float* verts = (const float*)d_in[0];
    const float* feat  = (const float*)d_in[1];
    const float* W1    = (const float*)d_in[2];
    const float* b1    = (const float*)d_in[3];
    const float* g1    = (const float*)d_in[4];
    const float* be1   = (const float*)d_in[5];
    const float* W2    = (const float*)d_in[6];
    const float* b2    = (const float*)d_in[7];
    const float* Wo1   = (const float*)d_in[8];
    const float* bo1   = (const float*)d_in[9];
    const float* go    = (const float*)d_in[10];
    const float* beo   = (const float*)d_in[11];
    const float* Wo2   = (const float*)d_in[12];
    const float* bo2   = (const float*)d_in[13];
    float* out = (float*)d_out;

    const int smem2 = SMEM2_FLOATS * 4;   // 81920
    cudaFuncSetAttribute(mlp2_kernel, cudaFuncAttributeMaxDynamicSharedMemorySize, smem2);

    prep_kernel<<<(TOT + 255)/256, 256>>>(verts);
    bin_kernel<<<(TOT + 255)/256, 256>>>();
    scan_kernel<<<BN, 1024>>>();
    scatter_kernel<<<(TOT + 255)/256, 256>>>();
    knn_kernel<<<TOT/8, 256>>>();
    precomp_kernel<<<TOT/8, 256>>>(verts, feat, W1, b1);
    edge_kernel<<<TOT/8, 256>>>(g1, be1, W2, b2);
    mlp2_kernel<<<TOT/M2PTS, 256, smem2>>>(Wo1, bo1, go, beo, Wo2, bo2, out);
}